// round 2
// baseline (speedup 1.0000x reference)
#include <cuda_runtime.h>
#include <math.h>

#define N_PTS 524288

// ---------------- scratch (device globals; no allocation) ----------------
__device__ float4 d_g0t[32 * 32 * 32];
__device__ float4 d_g1t[64 * 64 * 64];
__device__ float4 d_g2t[128 * 128 * 128];
__device__ float4 d_g3t[256 * 256 * 256];
__device__ float4 d_coeft[64 * 64 * 64];
__device__ float  d_feats[16 * N_PTS];   // transposed: feats[k][pt]

// ---------------- f32x2 packed helpers (Blackwell) ----------------
__device__ __forceinline__ unsigned long long splat_f32x2(float v) {
    unsigned long long r;
    unsigned int u = __float_as_uint(v);
    asm("mov.b64 %0, {%1, %1};" : "=l"(r) : "r"(u));
    return r;
}
__device__ __forceinline__ void ffma2(unsigned long long& d,
                                      unsigned long long a,
                                      unsigned long long b) {
    asm("fma.rn.f32x2 %0, %1, %2, %0;" : "+l"(d) : "l"(a), "l"(b));
}
__device__ __forceinline__ void unpack2(unsigned long long v, float& lo, float& hi) {
    unsigned int a, b;
    asm("mov.b64 {%0, %1}, %2;" : "=r"(a), "=r"(b) : "l"(v));
    lo = __uint_as_float(a);
    hi = __uint_as_float(b);
}

// ---------------- channels-last transpose: [4,V] -> [V] float4 ----------------
__global__ void transpose_cl(const float* __restrict__ src, float4* __restrict__ dst, int V) {
    int v = blockIdx.x * blockDim.x + threadIdx.x;
    if (v < V) {
        dst[v] = make_float4(src[v], src[v + V], src[v + 2 * V], src[v + 3 * V]);
    }
}

// ---------------- trilerp on channels-last grid ----------------
__device__ __forceinline__ float4 trilerp4(const float4* __restrict__ g, int R,
                                           float px, float py, float pz) {
    float s = 0.5f * (float)(R - 1);
    float cx = (px + 1.0f) * s;
    float cy = (py + 1.0f) * s;
    float cz = (pz + 1.0f) * s;
    float fx0 = floorf(cx), fy0 = floorf(cy), fz0 = floorf(cz);
    float fx = cx - fx0, fy = cy - fy0, fz = cz - fz0;
    int x0 = min(max((int)fx0, 0), R - 1);
    int y0 = min(max((int)fy0, 0), R - 1);
    int z0 = min(max((int)fz0, 0), R - 1);
    int x1 = min(x0 + 1, R - 1);
    int y1 = min(y0 + 1, R - 1);
    int z1 = min(z0 + 1, R - 1);

    const float4 v000 = __ldg(&g[(z0 * R + y0) * R + x0]);
    const float4 v001 = __ldg(&g[(z0 * R + y0) * R + x1]);
    const float4 v010 = __ldg(&g[(z0 * R + y1) * R + x0]);
    const float4 v011 = __ldg(&g[(z0 * R + y1) * R + x1]);
    const float4 v100 = __ldg(&g[(z1 * R + y0) * R + x0]);
    const float4 v101 = __ldg(&g[(z1 * R + y0) * R + x1]);
    const float4 v110 = __ldg(&g[(z1 * R + y1) * R + x0]);
    const float4 v111 = __ldg(&g[(z1 * R + y1) * R + x1]);

    float gx = 1.0f - fx, gy = 1.0f - fy, gz = 1.0f - fz;
    float w00 = gz * gy, w01 = gz * fy, w10 = fz * gy, w11 = fz * fy;

    float4 r;
    r.x = (v000.x * gx + v001.x * fx) * w00 + (v010.x * gx + v011.x * fx) * w01
        + (v100.x * gx + v101.x * fx) * w10 + (v110.x * gx + v111.x * fx) * w11;
    r.y = (v000.y * gx + v001.y * fx) * w00 + (v010.y * gx + v011.y * fx) * w01
        + (v100.y * gx + v101.y * fx) * w10 + (v110.y * gx + v111.y * fx) * w11;
    r.z = (v000.z * gx + v001.z * fx) * w00 + (v010.z * gx + v011.z * fx) * w01
        + (v100.z * gx + v101.z * fx) * w10 + (v110.z * gx + v111.z * fx) * w11;
    r.w = (v000.w * gx + v001.w * fx) * w00 + (v010.w * gx + v011.w * fx) * w01
        + (v100.w * gx + v101.w * fx) * w10 + (v110.w * gx + v111.w * fx) * w11;
    return r;
}

__device__ __forceinline__ float fracf(float a) { return a - floorf(a); }

// ---------------- encode: grids -> 16 features per point ----------------
__global__ void encode_kernel(const float* __restrict__ x) {
    int i = blockIdx.x * blockDim.x + threadIdx.x;
    if (i >= N_PTS) return;
    float px = x[3 * i + 0];
    float py = x[3 * i + 1];
    float pz = x[3 * i + 2];

    float4 coef = trilerp4(d_coeft, 64, px, py, pz);

    {
        float ex = 2.0f * fracf(px) - 1.0f;
        float ey = 2.0f * fracf(py) - 1.0f;
        float ez = 2.0f * fracf(pz) - 1.0f;
        float4 v = trilerp4(d_g0t, 32, ex, ey, ez);
        d_feats[0 * N_PTS + i] = v.x * coef.x;
        d_feats[1 * N_PTS + i] = v.y * coef.x;
        d_feats[2 * N_PTS + i] = v.z * coef.x;
        d_feats[3 * N_PTS + i] = v.w * coef.x;
    }
    {
        float ex = 2.0f * fracf(px * 2.0f) - 1.0f;
        float ey = 2.0f * fracf(py * 2.0f) - 1.0f;
        float ez = 2.0f * fracf(pz * 2.0f) - 1.0f;
        float4 v = trilerp4(d_g1t, 64, ex, ey, ez);
        d_feats[4 * N_PTS + i] = v.x * coef.y;
        d_feats[5 * N_PTS + i] = v.y * coef.y;
        d_feats[6 * N_PTS + i] = v.z * coef.y;
        d_feats[7 * N_PTS + i] = v.w * coef.y;
    }
    {
        float ex = 2.0f * fracf(px * 4.0f) - 1.0f;
        float ey = 2.0f * fracf(py * 4.0f) - 1.0f;
        float ez = 2.0f * fracf(pz * 4.0f) - 1.0f;
        float4 v = trilerp4(d_g2t, 128, ex, ey, ez);
        d_feats[8 * N_PTS + i]  = v.x * coef.z;
        d_feats[9 * N_PTS + i]  = v.y * coef.z;
        d_feats[10 * N_PTS + i] = v.z * coef.z;
        d_feats[11 * N_PTS + i] = v.w * coef.z;
    }
    {
        float ex = 2.0f * fracf(px * 8.0f) - 1.0f;
        float ey = 2.0f * fracf(py * 8.0f) - 1.0f;
        float ez = 2.0f * fracf(pz * 8.0f) - 1.0f;
        float4 v = trilerp4(d_g3t, 256, ex, ey, ez);
        d_feats[12 * N_PTS + i] = v.x * coef.w;
        d_feats[13 * N_PTS + i] = v.y * coef.w;
        d_feats[14 * N_PTS + i] = v.z * coef.w;
        d_feats[15 * N_PTS + i] = v.w * coef.w;
    }
}

// ---------------- MLP (FFMA2 / f32x2 packed) ----------------
// Block: 256 threads. Tile: 256 points x 128 outputs.
// smem: hbuf[k][pt] = [128][256] f32 (128KB), wsm[k][j] = [128][128] f32 (64KB).
// Thread (ptg = tid&31, og = tid>>5): 8 points x 16 outputs.
// The f32x2 vector runs along POINTS: adjacent points in hbuf give free
// (h_p0,h_p1) packing via a single 64-bit LDS; only w needs a splat.
struct MLPW {
    const float* W[7];
    const float* B[7];
};

__global__ void __launch_bounds__(256, 1) mlp_kernel(MLPW p, float* __restrict__ out) {
    extern __shared__ float sm[];
    float* hbuf = sm;                 // 128*256 floats
    float* wsm  = sm + 128 * 256;     // 128*128 floats

    const int tid  = threadIdx.x;
    const int base = blockIdx.x * 256;
    const int ptg  = tid & 31;
    const int og   = tid >> 5;
    const int pts  = ptg * 8;
    const int outs = og * 16;

    // stage layer-0 input (16 rows x 256 pts), coalesced
#pragma unroll
    for (int r = 0; r < 16; r++) {
        hbuf[r * 256 + tid] = d_feats[r * N_PTS + base + tid];
    }

    for (int l = 0; l < 7; l++) {
        const int K = (l == 0) ? 16 : 128;

        // stage W[l] into smem (K*128 floats), float4 coalesced
        const float4* wg = (const float4*)p.W[l];
        float4* wsd = (float4*)wsm;
        const int nw4 = (K * 128) / 4;
        for (int idx = tid; idx < nw4; idx += 256) wsd[idx] = __ldg(&wg[idx]);
        __syncthreads();

        float bv[16];
#pragma unroll
        for (int oi = 0; oi < 16; oi++) bv[oi] = __ldg(&p.B[l][outs + oi]);

        // acc2[pp][oi] packs points (2pp, 2pp+1) for output oi
        unsigned long long acc2[4][16];
#pragma unroll
        for (int pp = 0; pp < 4; pp++)
#pragma unroll
            for (int oi = 0; oi < 16; oi++) acc2[pp][oi] = 0ULL;

#pragma unroll 2
        for (int k = 0; k < K; k++) {
            const unsigned long long* hp =
                (const unsigned long long*)(hbuf + k * 256 + pts);
            const unsigned long long h0 = hp[0];
            const unsigned long long h1 = hp[1];
            const unsigned long long h2 = hp[2];
            const unsigned long long h3 = hp[3];

            const float4* wr = (const float4*)(wsm + k * 128 + outs);
            const float4 w0 = wr[0], w1 = wr[1], w2 = wr[2], w3 = wr[3];
            const float wv[16] = {w0.x, w0.y, w0.z, w0.w, w1.x, w1.y, w1.z, w1.w,
                                  w2.x, w2.y, w2.z, w2.w, w3.x, w3.y, w3.z, w3.w};
#pragma unroll
            for (int oi = 0; oi < 16; oi++) {
                const unsigned long long ws = splat_f32x2(wv[oi]);
                ffma2(acc2[0][oi], h0, ws);
                ffma2(acc2[1][oi], h1, ws);
                ffma2(acc2[2][oi], h2, ws);
                ffma2(acc2[3][oi], h3, ws);
            }
        }
        __syncthreads();

        if (l < 6) {
            // relu(acc + b) -> hbuf[j][pt] for next layer (8-byte stores)
#pragma unroll
            for (int oi = 0; oi < 16; oi++) {
                const int j = outs + oi;
#pragma unroll
                for (int pp = 0; pp < 4; pp++) {
                    float lo, hi;
                    unpack2(acc2[pp][oi], lo, hi);
                    float2 v;
                    v.x = fmaxf(lo + bv[oi], 0.0f);
                    v.y = fmaxf(hi + bv[oi], 0.0f);
                    *(float2*)(hbuf + j * 256 + pts + 2 * pp) = v;
                }
            }
        } else {
            // final layer: acc + b -> global out [N,128]
#pragma unroll
            for (int pp = 0; pp < 4; pp++) {
                float* row0 = out + (size_t)(base + pts + 2 * pp + 0) * 128 + outs;
                float* row1 = out + (size_t)(base + pts + 2 * pp + 1) * 128 + outs;
#pragma unroll
                for (int oq = 0; oq < 4; oq++) {
                    float4 o0, o1;
                    float lo, hi;
                    unpack2(acc2[pp][oq * 4 + 0], lo, hi);
                    o0.x = lo + bv[oq * 4 + 0]; o1.x = hi + bv[oq * 4 + 0];
                    unpack2(acc2[pp][oq * 4 + 1], lo, hi);
                    o0.y = lo + bv[oq * 4 + 1]; o1.y = hi + bv[oq * 4 + 1];
                    unpack2(acc2[pp][oq * 4 + 2], lo, hi);
                    o0.z = lo + bv[oq * 4 + 2]; o1.z = hi + bv[oq * 4 + 2];
                    unpack2(acc2[pp][oq * 4 + 3], lo, hi);
                    o0.w = lo + bv[oq * 4 + 3]; o1.w = hi + bv[oq * 4 + 3];
                    *(float4*)(row0 + oq * 4) = o0;
                    *(float4*)(row1 + oq * 4) = o1;
                }
            }
        }
    }
}

// ---------------- launch ----------------
extern "C" void kernel_launch(void* const* d_in, const int* in_sizes, int n_in,
                              void* d_out, int out_size) {
    const float* x    = (const float*)d_in[0];
    const float* g0   = (const float*)d_in[1];
    const float* g1   = (const float*)d_in[2];
    const float* g2   = (const float*)d_in[3];
    const float* g3   = (const float*)d_in[4];
    const float* coef = (const float*)d_in[5];

    MLPW p;
    for (int j = 0; j < 7; j++) {
        p.W[j] = (const float*)d_in[6 + 2 * j];
        p.B[j] = (const float*)d_in[7 + 2 * j];
    }
    float* out = (float*)d_out;

    cudaFuncSetAttribute(mlp_kernel, cudaFuncAttributeMaxDynamicSharedMemorySize,
                         (128 * 256 + 128 * 128) * 4);

    void* ptr;
    cudaGetSymbolAddress(&ptr, d_g0t);   float4* g0t = (float4*)ptr;
    cudaGetSymbolAddress(&ptr, d_g1t);   float4* g1t = (float4*)ptr;
    cudaGetSymbolAddress(&ptr, d_g2t);   float4* g2t = (float4*)ptr;
    cudaGetSymbolAddress(&ptr, d_g3t);   float4* g3t = (float4*)ptr;
    cudaGetSymbolAddress(&ptr, d_coeft); float4* ct  = (float4*)ptr;

    transpose_cl<<<(32 * 32 * 32 + 255) / 256, 256>>>(g0, g0t, 32 * 32 * 32);
    transpose_cl<<<(64 * 64 * 64 + 255) / 256, 256>>>(g1, g1t, 64 * 64 * 64);
    transpose_cl<<<(128 * 128 * 128 + 255) / 256, 256>>>(g2, g2t, 128 * 128 * 128);
    transpose_cl<<<(256 * 256 * 256 + 255) / 256, 256>>>(g3, g3t, 256 * 256 * 256);
    transpose_cl<<<(64 * 64 * 64 + 255) / 256, 256>>>(coef, ct, 64 * 64 * 64);

    encode_kernel<<<N_PTS / 256, 256>>>(x);

    mlp_kernel<<<N_PTS / 256, 256, (128 * 256 + 128 * 128) * 4>>>(p, out);
}

// round 4
// speedup vs baseline: 2.2739x; 2.2739x over previous
#include <cuda_runtime.h>
#include <cuda_bf16.h>
#include <math.h>
#include <stdint.h>

#define N_PTS 524288

// ---------------- scratch (device globals; no allocation) ----------------
__device__ float4 d_g0t[32 * 32 * 32];
__device__ float4 d_g1t[64 * 64 * 64];
__device__ float4 d_g2t[128 * 128 * 128];
__device__ float4 d_g3t[256 * 256 * 256];
__device__ float4 d_coeft[64 * 64 * 64];
__device__ float  d_feats[16 * N_PTS];   // transposed: feats[k][pt]
// packed weight fragments: [7 layers][kstep 8][ntile 16][lane 32] x uint4
// uint4 = {Bh.b0, Bh.b1, Bl.b0, Bl.b1} in mma.m16n8k16 col-B fragment layout.
__device__ __align__(16) unsigned char d_wpack[7 * 65536];

// ================= helpers =================
__device__ __forceinline__ uint32_t smem_to_u32(const void* p) {
    uint32_t a;
    asm("{ .reg .u64 t; cvta.to.shared.u64 t, %1; cvt.u32.u64 %0, t; }"
        : "=r"(a) : "l"(p));
    return a;
}
// pack two f32 -> bf16x2 (low half = v0)
__device__ __forceinline__ uint32_t cvt_bf16x2(float v0, float v1) {
    uint32_t d;
    asm("cvt.rn.bf16x2.f32 %0, %1, %2;" : "=r"(d) : "f"(v1), "f"(v0));
    return d;
}
// split (v0,v1) into bf16x2 hi + bf16x2 lo (residual)
__device__ __forceinline__ void split2(float v0, float v1, uint32_t& hi, uint32_t& lo) {
    hi = cvt_bf16x2(v0, v1);
    float h0 = __uint_as_float(hi << 16);
    float h1 = __uint_as_float(hi & 0xffff0000u);
    lo = cvt_bf16x2(v0 - h0, v1 - h1);
}
__device__ __forceinline__ void mma_bf16(float* c, const uint32_t* a,
                                         uint32_t b0, uint32_t b1) {
    asm volatile(
        "mma.sync.aligned.m16n8k16.row.col.f32.bf16.bf16.f32 "
        "{%0,%1,%2,%3}, {%4,%5,%6,%7}, {%8,%9}, {%0,%1,%2,%3};"
        : "+f"(c[0]), "+f"(c[1]), "+f"(c[2]), "+f"(c[3])
        : "r"(a[0]), "r"(a[1]), "r"(a[2]), "r"(a[3]), "r"(b0), "r"(b1));
}
__device__ __forceinline__ void cp_async16(uint32_t smem_dst, const void* gsrc) {
    asm volatile("cp.async.cg.shared.global [%0], [%1], 16;"
                 :: "r"(smem_dst), "l"(gsrc));
}
__device__ __forceinline__ void cp_commit() {
    asm volatile("cp.async.commit_group;" ::: "memory");
}
__device__ __forceinline__ void cp_wait_all() {
    asm volatile("cp.async.wait_group 0;" ::: "memory");
}

// ---------------- channels-last transpose: [4,V] -> [V] float4 ----------------
__global__ void transpose_cl(const float* __restrict__ src, float4* __restrict__ dst, int V) {
    int v = blockIdx.x * blockDim.x + threadIdx.x;
    if (v < V) {
        dst[v] = make_float4(src[v], src[v + V], src[v + 2 * V], src[v + 3 * V]);
    }
}

// ---------------- weight packer ----------------
struct MLPW {
    const float* W[7];
    const float* B[7];
};

// fragment layout for mma.m16n8k16 row.col, B is [K,128] row-major in memory:
// b0 = {B[k0][n], B[k0+1][n]}, b1 = {B[k0+8][n], B[k0+9][n]},
// k0 = 16*kstep + 2*(lane&3), n = 8*ntile + (lane>>2)
__global__ void pack_weights(MLPW p) {
    int t = blockIdx.x * blockDim.x + threadIdx.x;
    if (t >= 7 * 8 * 16 * 32) return;
    int l     = t >> 12;
    int r     = t & 4095;
    int kstep = r >> 9;
    int ntile = (r >> 5) & 15;
    int lane  = r & 31;

    uint4 frag = make_uint4(0, 0, 0, 0);
    if (!(l == 0 && kstep > 0)) {
        int n  = ntile * 8 + (lane >> 2);
        int k0 = kstep * 16 + 2 * (lane & 3);
        const float* W = p.W[l];
        float w00 = W[(k0 + 0) * 128 + n];
        float w01 = W[(k0 + 1) * 128 + n];
        float w08 = W[(k0 + 8) * 128 + n];
        float w09 = W[(k0 + 9) * 128 + n];
        uint32_t h0, l0, h1, l1;
        split2(w00, w01, h0, l0);
        split2(w08, w09, h1, l1);
        frag = make_uint4(h0, h1, l0, l1);
    }
    *(uint4*)(d_wpack + (size_t)l * 65536 + (size_t)r * 16) = frag;
}

// ---------------- trilerp on channels-last grid ----------------
__device__ __forceinline__ float4 trilerp4(const float4* __restrict__ g, int R,
                                           float px, float py, float pz) {
    float s = 0.5f * (float)(R - 1);
    float cx = (px + 1.0f) * s;
    float cy = (py + 1.0f) * s;
    float cz = (pz + 1.0f) * s;
    float fx0 = floorf(cx), fy0 = floorf(cy), fz0 = floorf(cz);
    float fx = cx - fx0, fy = cy - fy0, fz = cz - fz0;
    int x0 = min(max((int)fx0, 0), R - 1);
    int y0 = min(max((int)fy0, 0), R - 1);
    int z0 = min(max((int)fz0, 0), R - 1);
    int x1 = min(x0 + 1, R - 1);
    int y1 = min(y0 + 1, R - 1);
    int z1 = min(z0 + 1, R - 1);

    const float4 v000 = __ldg(&g[(z0 * R + y0) * R + x0]);
    const float4 v001 = __ldg(&g[(z0 * R + y0) * R + x1]);
    const float4 v010 = __ldg(&g[(z0 * R + y1) * R + x0]);
    const float4 v011 = __ldg(&g[(z0 * R + y1) * R + x1]);
    const float4 v100 = __ldg(&g[(z1 * R + y0) * R + x0]);
    const float4 v101 = __ldg(&g[(z1 * R + y0) * R + x1]);
    const float4 v110 = __ldg(&g[(z1 * R + y1) * R + x0]);
    const float4 v111 = __ldg(&g[(z1 * R + y1) * R + x1]);

    float gx = 1.0f - fx, gy = 1.0f - fy, gz = 1.0f - fz;
    float w00 = gz * gy, w01 = gz * fy, w10 = fz * gy, w11 = fz * fy;

    float4 r;
    r.x = (v000.x * gx + v001.x * fx) * w00 + (v010.x * gx + v011.x * fx) * w01
        + (v100.x * gx + v101.x * fx) * w10 + (v110.x * gx + v111.x * fx) * w11;
    r.y = (v000.y * gx + v001.y * fx) * w00 + (v010.y * gx + v011.y * fx) * w01
        + (v100.y * gx + v101.y * fx) * w10 + (v110.y * gx + v111.y * fx) * w11;
    r.z = (v000.z * gx + v001.z * fx) * w00 + (v010.z * gx + v011.z * fx) * w01
        + (v100.z * gx + v101.z * fx) * w10 + (v110.z * gx + v111.z * fx) * w11;
    r.w = (v000.w * gx + v001.w * fx) * w00 + (v010.w * gx + v011.w * fx) * w01
        + (v100.w * gx + v101.w * fx) * w10 + (v110.w * gx + v111.w * fx) * w11;
    return r;
}

__device__ __forceinline__ float fracf(float a) { return a - floorf(a); }

// ---------------- encode: grids -> 16 features per point ----------------
__global__ void encode_kernel(const float* __restrict__ x) {
    int i = blockIdx.x * blockDim.x + threadIdx.x;
    if (i >= N_PTS) return;
    float px = x[3 * i + 0];
    float py = x[3 * i + 1];
    float pz = x[3 * i + 2];

    float4 coef = trilerp4(d_coeft, 64, px, py, pz);

    {
        float ex = 2.0f * fracf(px) - 1.0f;
        float ey = 2.0f * fracf(py) - 1.0f;
        float ez = 2.0f * fracf(pz) - 1.0f;
        float4 v = trilerp4(d_g0t, 32, ex, ey, ez);
        d_feats[0 * N_PTS + i] = v.x * coef.x;
        d_feats[1 * N_PTS + i] = v.y * coef.x;
        d_feats[2 * N_PTS + i] = v.z * coef.x;
        d_feats[3 * N_PTS + i] = v.w * coef.x;
    }
    {
        float ex = 2.0f * fracf(px * 2.0f) - 1.0f;
        float ey = 2.0f * fracf(py * 2.0f) - 1.0f;
        float ez = 2.0f * fracf(pz * 2.0f) - 1.0f;
        float4 v = trilerp4(d_g1t, 64, ex, ey, ez);
        d_feats[4 * N_PTS + i] = v.x * coef.y;
        d_feats[5 * N_PTS + i] = v.y * coef.y;
        d_feats[6 * N_PTS + i] = v.z * coef.y;
        d_feats[7 * N_PTS + i] = v.w * coef.y;
    }
    {
        float ex = 2.0f * fracf(px * 4.0f) - 1.0f;
        float ey = 2.0f * fracf(py * 4.0f) - 1.0f;
        float ez = 2.0f * fracf(pz * 4.0f) - 1.0f;
        float4 v = trilerp4(d_g2t, 128, ex, ey, ez);
        d_feats[8 * N_PTS + i]  = v.x * coef.z;
        d_feats[9 * N_PTS + i]  = v.y * coef.z;
        d_feats[10 * N_PTS + i] = v.z * coef.z;
        d_feats[11 * N_PTS + i] = v.w * coef.z;
    }
    {
        float ex = 2.0f * fracf(px * 8.0f) - 1.0f;
        float ey = 2.0f * fracf(py * 8.0f) - 1.0f;
        float ez = 2.0f * fracf(pz * 8.0f) - 1.0f;
        float4 v = trilerp4(d_g3t, 256, ex, ey, ez);
        d_feats[12 * N_PTS + i] = v.x * coef.w;
        d_feats[13 * N_PTS + i] = v.y * coef.w;
        d_feats[14 * N_PTS + i] = v.z * coef.w;
        d_feats[15 * N_PTS + i] = v.w * coef.w;
    }
}

// ---------------- tensor-core MLP via mma.sync (baseline PTX) ----------------
// CTA = 256 threads (8 warps), tile = 128 points. Warp w owns rows
// [16w, 16w+16): full 7-layer chain stays warp-local in registers.
// smem: 2x 64KB weight-fragment buffers (double-buffered via cp.async) + 2x bias.
#define SM_WBUF 65536
#define SM_BIAS (2 * SM_WBUF)
#define SM_DYN  (2 * SM_WBUF + 2 * 512)

__global__ void __launch_bounds__(256) mlp_mma(MLPW p, float* __restrict__ out) {
    extern __shared__ char smem[];
    const int tid  = threadIdx.x;
    const int wid  = tid >> 5;
    const int lane = tid & 31;
    const int g    = lane >> 2;
    const int tc   = lane & 3;
    const int base = blockIdx.x * 128;
    const int r0   = base + wid * 16 + g;
    const int r1   = r0 + 8;

    const uint4* wbuf[2] = {(const uint4*)smem, (const uint4*)(smem + SM_WBUF)};
    const float* bias[2] = {(const float*)(smem + SM_BIAS),
                            (const float*)(smem + SM_BIAS + 512)};
    const uint32_t sb = smem_to_u32(smem);

    // --- prefetch layer-0 weights (512 frags) + bias ---
    {
        for (int i = tid; i < 512; i += 256)
            cp_async16(sb + 16 * i, d_wpack + 16 * (size_t)i);
        if (tid < 32)
            cp_async16(sb + SM_BIAS + 16 * tid, (const char*)p.B[0] + 16 * tid);
        cp_commit();
    }

    // --- build layer-0 A fragments from feats (kstep 0 only) ---
    uint32_t ahi[8][4], alo[8][4];
    {
        const int k0 = 2 * tc;
        float a00 = d_feats[(k0 + 0) * N_PTS + r0];
        float a01 = d_feats[(k0 + 1) * N_PTS + r0];
        float a10 = d_feats[(k0 + 0) * N_PTS + r1];
        float a11 = d_feats[(k0 + 1) * N_PTS + r1];
        float a02 = d_feats[(k0 + 8) * N_PTS + r0];
        float a03 = d_feats[(k0 + 9) * N_PTS + r0];
        float a12 = d_feats[(k0 + 8) * N_PTS + r1];
        float a13 = d_feats[(k0 + 9) * N_PTS + r1];
        split2(a00, a01, ahi[0][0], alo[0][0]);
        split2(a10, a11, ahi[0][1], alo[0][1]);
        split2(a02, a03, ahi[0][2], alo[0][2]);
        split2(a12, a13, ahi[0][3], alo[0][3]);
    }

    for (int l = 0; l < 7; l++) {
        const int K16 = (l == 0) ? 1 : 8;
        const int cur = l & 1;

        cp_wait_all();
        __syncthreads();

        // kick off next layer's weights + bias into the other buffer
        if (l < 6) {
            const char* src = (const char*)(d_wpack + (size_t)(l + 1) * 65536);
            uint32_t dst = sb + ((l + 1) & 1) * SM_WBUF;
            for (int i = tid; i < 4096; i += 256)
                cp_async16(dst + 16 * i, src + 16 * (size_t)i);
            if (tid < 32)
                cp_async16(sb + SM_BIAS + ((l + 1) & 1) * 512 + 16 * tid,
                           (const char*)p.B[l + 1] + 16 * tid);
            cp_commit();
        }

        float acc[16][4];
#pragma unroll
        for (int j = 0; j < 16; j++)
#pragma unroll
            for (int q = 0; q < 4; q++) acc[j][q] = 0.0f;

        const uint4* wf = wbuf[cur];
#pragma unroll 1
        for (int ks = 0; ks < K16; ks++) {
#pragma unroll
            for (int j = 0; j < 16; j++) {
                uint4 w = wf[(ks * 16 + j) * 32 + lane];
                mma_bf16(acc[j], ahi[ks], w.x, w.y);   // Ah * Bh
                mma_bf16(acc[j], alo[ks], w.x, w.y);   // Al * Bh
                mma_bf16(acc[j], ahi[ks], w.z, w.w);   // Ah * Bl
            }
        }

        const float* bs = bias[cur];
        if (l < 6) {
            // bias + relu, then repack D -> next-layer A fragments (lane-local)
#pragma unroll
            for (int j = 0; j < 16; j++) {
                float b0 = bs[8 * j + 2 * tc];
                float b1 = bs[8 * j + 2 * tc + 1];
                acc[j][0] = fmaxf(acc[j][0] + b0, 0.0f);
                acc[j][1] = fmaxf(acc[j][1] + b1, 0.0f);
                acc[j][2] = fmaxf(acc[j][2] + b0, 0.0f);
                acc[j][3] = fmaxf(acc[j][3] + b1, 0.0f);
            }
#pragma unroll
            for (int t = 0; t < 8; t++) {
                split2(acc[2 * t][0],     acc[2 * t][1],     ahi[t][0], alo[t][0]);
                split2(acc[2 * t][2],     acc[2 * t][3],     ahi[t][1], alo[t][1]);
                split2(acc[2 * t + 1][0], acc[2 * t + 1][1], ahi[t][2], alo[t][2]);
                split2(acc[2 * t + 1][2], acc[2 * t + 1][3], ahi[t][3], alo[t][3]);
            }
        } else {
            float* o0 = out + (size_t)r0 * 128;
            float* o1 = out + (size_t)r1 * 128;
#pragma unroll
            for (int j = 0; j < 16; j++) {
                const int col = 8 * j + 2 * tc;
                float b0 = bs[col], b1 = bs[col + 1];
                float2 v0 = make_float2(acc[j][0] + b0, acc[j][1] + b1);
                float2 v1 = make_float2(acc[j][2] + b0, acc[j][3] + b1);
                *(float2*)(o0 + col) = v0;
                *(float2*)(o1 + col) = v1;
            }
        }
    }
}

// ---------------- launch ----------------
extern "C" void kernel_launch(void* const* d_in, const int* in_sizes, int n_in,
                              void* d_out, int out_size) {
    const float* x    = (const float*)d_in[0];
    const float* g0   = (const float*)d_in[1];
    const float* g1   = (const float*)d_in[2];
    const float* g2   = (const float*)d_in[3];
    const float* g3   = (const float*)d_in[4];
    const float* coef = (const float*)d_in[5];

    MLPW p;
    for (int j = 0; j < 7; j++) {
        p.W[j] = (const float*)d_in[6 + 2 * j];
        p.B[j] = (const float*)d_in[7 + 2 * j];
    }
    float* out = (float*)d_out;

    cudaFuncSetAttribute(mlp_mma, cudaFuncAttributeMaxDynamicSharedMemorySize, SM_DYN);

    void* ptr;
    cudaGetSymbolAddress(&ptr, d_g0t);   float4* g0t = (float4*)ptr;
    cudaGetSymbolAddress(&ptr, d_g1t);   float4* g1t = (float4*)ptr;
    cudaGetSymbolAddress(&ptr, d_g2t);   float4* g2t = (float4*)ptr;
    cudaGetSymbolAddress(&ptr, d_g3t);   float4* g3t = (float4*)ptr;
    cudaGetSymbolAddress(&ptr, d_coeft); float4* ct  = (float4*)ptr;

    transpose_cl<<<(32 * 32 * 32 + 255) / 256, 256>>>(g0, g0t, 32 * 32 * 32);
    transpose_cl<<<(64 * 64 * 64 + 255) / 256, 256>>>(g1, g1t, 64 * 64 * 64);
    transpose_cl<<<(128 * 128 * 128 + 255) / 256, 256>>>(g2, g2t, 128 * 128 * 128);
    transpose_cl<<<(256 * 256 * 256 + 255) / 256, 256>>>(g3, g3t, 256 * 256 * 256);
    transpose_cl<<<(64 * 64 * 64 + 255) / 256, 256>>>(coef, ct, 64 * 64 * 64);

    pack_weights<<<(7 * 8 * 16 * 32 + 255) / 256, 256>>>(p);

    encode_kernel<<<N_PTS / 256, 256>>>(x);

    mlp_mma<<<N_PTS / 128, 256, SM_DYN>>>(p, out);
}

// round 5
// speedup vs baseline: 2.7849x; 1.2247x over previous
#include <cuda_runtime.h>
#include <cuda_fp16.h>
#include <math.h>
#include <stdint.h>

#define N_PTS 524288

// ---------------- scratch (device globals; no allocation) ----------------
__device__ float4 d_g0t[32 * 32 * 32];
__device__ float4 d_g1t[64 * 64 * 64];
__device__ float4 d_g2t[128 * 128 * 128];
__device__ float4 d_g3t[256 * 256 * 256];
__device__ float4 d_coeft[64 * 64 * 64];
// packed weight fragments: [7 layers][kstep 8][ntile 16][lane 32] x uint4
// uint4 = {Bh.b0, Bh.b1, Bl.b0, Bl.b1} (fp16x2) in mma.m16n8k16 col-B layout.
__device__ __align__(16) unsigned char d_wpack[7 * 65536];

// ================= helpers =================
__device__ __forceinline__ uint32_t smem_to_u32(const void* p) {
    uint32_t a;
    asm("{ .reg .u64 t; cvta.to.shared.u64 t, %1; cvt.u32.u64 %0, t; }"
        : "=r"(a) : "l"(p));
    return a;
}
// pack two f32 -> f16x2 (low half = v0)
__device__ __forceinline__ uint32_t cvt_f16x2(float v0, float v1) {
    uint32_t d;
    asm("cvt.rn.f16x2.f32 %0, %1, %2;" : "=r"(d) : "f"(v1), "f"(v0));
    return d;
}
__device__ __forceinline__ void mma_fp16(float* c, const uint32_t* a,
                                         uint32_t b0, uint32_t b1) {
    asm volatile(
        "mma.sync.aligned.m16n8k16.row.col.f32.f16.f16.f32 "
        "{%0,%1,%2,%3}, {%4,%5,%6,%7}, {%8,%9}, {%0,%1,%2,%3};"
        : "+f"(c[0]), "+f"(c[1]), "+f"(c[2]), "+f"(c[3])
        : "r"(a[0]), "r"(a[1]), "r"(a[2]), "r"(a[3]), "r"(b0), "r"(b1));
}
__device__ __forceinline__ void cp_async16(uint32_t smem_dst, const void* gsrc) {
    asm volatile("cp.async.cg.shared.global [%0], [%1], 16;"
                 :: "r"(smem_dst), "l"(gsrc));
}
__device__ __forceinline__ void cp_commit() {
    asm volatile("cp.async.commit_group;" ::: "memory");
}
__device__ __forceinline__ void cp_wait_all() {
    asm volatile("cp.async.wait_group 0;" ::: "memory");
}

// ---------------- channels-last transpose: [4,V] -> [V] float4 ----------------
__global__ void transpose_cl(const float* __restrict__ src, float4* __restrict__ dst, int V) {
    int v = blockIdx.x * blockDim.x + threadIdx.x;
    if (v < V) {
        dst[v] = make_float4(src[v], src[v + V], src[v + 2 * V], src[v + 3 * V]);
    }
}

// ---------------- weight packer ----------------
struct MLPW {
    const float* W[7];
    const float* B[7];
};

// fragment layout for mma.m16n8k16 row.col, B is [K,128] row-major in memory:
// b0 = {B[k0][n], B[k0+1][n]}, b1 = {B[k0+8][n], B[k0+9][n]},
// k0 = 16*kstep + 2*(lane&3), n = 8*ntile + (lane>>2)
// fp16 split: Bh = fp16(W), Bl = fp16(W - Bh)
__global__ void pack_weights(MLPW p) {
    int t = blockIdx.x * blockDim.x + threadIdx.x;
    if (t >= 7 * 8 * 16 * 32) return;
    int l     = t >> 12;
    int r     = t & 4095;
    int kstep = r >> 9;
    int ntile = (r >> 5) & 15;
    int lane  = r & 31;

    uint4 frag = make_uint4(0, 0, 0, 0);
    if (!(l == 0 && kstep > 0)) {
        int n  = ntile * 8 + (lane >> 2);
        int k0 = kstep * 16 + 2 * (lane & 3);
        const float* W = p.W[l];
        float w00 = W[(k0 + 0) * 128 + n];
        float w01 = W[(k0 + 1) * 128 + n];
        float w08 = W[(k0 + 8) * 128 + n];
        float w09 = W[(k0 + 9) * 128 + n];
        float h00 = __half2float(__float2half_rn(w00));
        float h01 = __half2float(__float2half_rn(w01));
        float h08 = __half2float(__float2half_rn(w08));
        float h09 = __half2float(__float2half_rn(w09));
        frag.x = cvt_f16x2(h00, h01);
        frag.y = cvt_f16x2(h08, h09);
        frag.z = cvt_f16x2(w00 - h00, w01 - h01);
        frag.w = cvt_f16x2(w08 - h08, w09 - h09);
    }
    *(uint4*)(d_wpack + (size_t)l * 65536 + (size_t)r * 16) = frag;
}

// ---------------- trilerp on channels-last grid ----------------
__device__ __forceinline__ float4 trilerp4(const float4* __restrict__ g, int R,
                                           float px, float py, float pz) {
    float s = 0.5f * (float)(R - 1);
    float cx = (px + 1.0f) * s;
    float cy = (py + 1.0f) * s;
    float cz = (pz + 1.0f) * s;
    float fx0 = floorf(cx), fy0 = floorf(cy), fz0 = floorf(cz);
    float fx = cx - fx0, fy = cy - fy0, fz = cz - fz0;
    int x0 = min(max((int)fx0, 0), R - 1);
    int y0 = min(max((int)fy0, 0), R - 1);
    int z0 = min(max((int)fz0, 0), R - 1);
    int x1 = min(x0 + 1, R - 1);
    int y1 = min(y0 + 1, R - 1);
    int z1 = min(z0 + 1, R - 1);

    const float4 v000 = __ldg(&g[(z0 * R + y0) * R + x0]);
    const float4 v001 = __ldg(&g[(z0 * R + y0) * R + x1]);
    const float4 v010 = __ldg(&g[(z0 * R + y1) * R + x0]);
    const float4 v011 = __ldg(&g[(z0 * R + y1) * R + x1]);
    const float4 v100 = __ldg(&g[(z1 * R + y0) * R + x0]);
    const float4 v101 = __ldg(&g[(z1 * R + y0) * R + x1]);
    const float4 v110 = __ldg(&g[(z1 * R + y1) * R + x0]);
    const float4 v111 = __ldg(&g[(z1 * R + y1) * R + x1]);

    float gx = 1.0f - fx, gy = 1.0f - fy, gz = 1.0f - fz;
    float w00 = gz * gy, w01 = gz * fy, w10 = fz * gy, w11 = fz * fy;

    float4 r;
    r.x = (v000.x * gx + v001.x * fx) * w00 + (v010.x * gx + v011.x * fx) * w01
        + (v100.x * gx + v101.x * fx) * w10 + (v110.x * gx + v111.x * fx) * w11;
    r.y = (v000.y * gx + v001.y * fx) * w00 + (v010.y * gx + v011.y * fx) * w01
        + (v100.y * gx + v101.y * fx) * w10 + (v110.y * gx + v111.y * fx) * w11;
    r.z = (v000.z * gx + v001.z * fx) * w00 + (v010.z * gx + v011.z * fx) * w01
        + (v100.z * gx + v101.z * fx) * w10 + (v110.z * gx + v111.z * fx) * w11;
    r.w = (v000.w * gx + v001.w * fx) * w00 + (v010.w * gx + v011.w * fx) * w01
        + (v100.w * gx + v101.w * fx) * w10 + (v110.w * gx + v111.w * fx) * w11;
    return r;
}

__device__ __forceinline__ float fracf(float a) { return a - floorf(a); }

// ---------------- fused encode + tensor-core MLP ----------------
// CTA = 256 threads (8 warps), tile = 128 points.
// Prologue: tid<128 gathers coef+g0+g1 for its point; tid>=128 gathers g2+g3.
// Feats staged in smem [16][128], then warp w owns rows [16w,16w+16) for the
// full 7-layer chain in registers (A fragments lane-local across layers).
// fp16 scheme: A single fp16, B split (Bh+Bl) -> 2 MMAs per k-step.
#define SM_WBUF 65536
#define SM_BIAS (2 * SM_WBUF)
#define SM_FEAT (SM_BIAS + 2 * 512)
#define SM_DYN  (SM_FEAT + 16 * 128 * 4)

__global__ void __launch_bounds__(256) mlp_mma(MLPW p, const float* __restrict__ x,
                                               float* __restrict__ out) {
    extern __shared__ char smem[];
    const int tid  = threadIdx.x;
    const int wid  = tid >> 5;
    const int lane = tid & 31;
    const int g    = lane >> 2;
    const int tc   = lane & 3;
    const int base = blockIdx.x * 128;

    const uint4* wbuf[2] = {(const uint4*)smem, (const uint4*)(smem + SM_WBUF)};
    const float* bias[2] = {(const float*)(smem + SM_BIAS),
                            (const float*)(smem + SM_BIAS + 512)};
    float* sfeat = (float*)(smem + SM_FEAT);   // [16][128]
    const uint32_t sb = smem_to_u32(smem);

    // --- prefetch layer-0 weights (512 frags) + bias ---
    for (int i = tid; i < 512; i += 256)
        cp_async16(sb + 16 * i, d_wpack + 16 * (size_t)i);
    if (tid < 32)
        cp_async16(sb + SM_BIAS + 16 * tid, (const char*)p.B[0] + 16 * tid);
    cp_commit();

    // --- fused encode: 2 threads per point ---
    {
        const int half = tid >> 7;
        const int pl   = tid & 127;
        const int i    = base + pl;
        float px = x[3 * i + 0];
        float py = x[3 * i + 1];
        float pz = x[3 * i + 2];
        float4 coef = trilerp4(d_coeft, 64, px, py, pz);

        if (half == 0) {
            {
                float ex = 2.0f * fracf(px) - 1.0f;
                float ey = 2.0f * fracf(py) - 1.0f;
                float ez = 2.0f * fracf(pz) - 1.0f;
                float4 v = trilerp4(d_g0t, 32, ex, ey, ez);
                sfeat[0 * 128 + pl] = v.x * coef.x;
                sfeat[1 * 128 + pl] = v.y * coef.x;
                sfeat[2 * 128 + pl] = v.z * coef.x;
                sfeat[3 * 128 + pl] = v.w * coef.x;
            }
            {
                float ex = 2.0f * fracf(px * 2.0f) - 1.0f;
                float ey = 2.0f * fracf(py * 2.0f) - 1.0f;
                float ez = 2.0f * fracf(pz * 2.0f) - 1.0f;
                float4 v = trilerp4(d_g1t, 64, ex, ey, ez);
                sfeat[4 * 128 + pl] = v.x * coef.y;
                sfeat[5 * 128 + pl] = v.y * coef.y;
                sfeat[6 * 128 + pl] = v.z * coef.y;
                sfeat[7 * 128 + pl] = v.w * coef.y;
            }
        } else {
            {
                float ex = 2.0f * fracf(px * 4.0f) - 1.0f;
                float ey = 2.0f * fracf(py * 4.0f) - 1.0f;
                float ez = 2.0f * fracf(pz * 4.0f) - 1.0f;
                float4 v = trilerp4(d_g2t, 128, ex, ey, ez);
                sfeat[8 * 128 + pl]  = v.x * coef.z;
                sfeat[9 * 128 + pl]  = v.y * coef.z;
                sfeat[10 * 128 + pl] = v.z * coef.z;
                sfeat[11 * 128 + pl] = v.w * coef.z;
            }
            {
                float ex = 2.0f * fracf(px * 8.0f) - 1.0f;
                float ey = 2.0f * fracf(py * 8.0f) - 1.0f;
                float ez = 2.0f * fracf(pz * 8.0f) - 1.0f;
                float4 v = trilerp4(d_g3t, 256, ex, ey, ez);
                sfeat[12 * 128 + pl] = v.x * coef.w;
                sfeat[13 * 128 + pl] = v.y * coef.w;
                sfeat[14 * 128 + pl] = v.z * coef.w;
                sfeat[15 * 128 + pl] = v.w * coef.w;
            }
        }
    }
    __syncthreads();

    // --- layer-0 A fragments (single fp16), kstep 0 only ---
    uint32_t af[8][4];
    {
        const int k0  = 2 * tc;
        const int rl0 = wid * 16 + g;
        const int rl1 = rl0 + 8;
        af[0][0] = cvt_f16x2(sfeat[(k0 + 0) * 128 + rl0], sfeat[(k0 + 1) * 128 + rl0]);
        af[0][1] = cvt_f16x2(sfeat[(k0 + 0) * 128 + rl1], sfeat[(k0 + 1) * 128 + rl1]);
        af[0][2] = cvt_f16x2(sfeat[(k0 + 8) * 128 + rl0], sfeat[(k0 + 9) * 128 + rl0]);
        af[0][3] = cvt_f16x2(sfeat[(k0 + 8) * 128 + rl1], sfeat[(k0 + 9) * 128 + rl1]);
    }

    const int r0 = base + wid * 16 + g;
    const int r1 = r0 + 8;

    for (int l = 0; l < 7; l++) {
        const int K16 = (l == 0) ? 1 : 8;
        const int cur = l & 1;

        cp_wait_all();
        __syncthreads();

        // kick off next layer's weights + bias into the other buffer
        if (l < 6) {
            const char* src = (const char*)(d_wpack + (size_t)(l + 1) * 65536);
            uint32_t dst = sb + ((l + 1) & 1) * SM_WBUF;
            for (int i = tid; i < 4096; i += 256)
                cp_async16(dst + 16 * i, src + 16 * (size_t)i);
            if (tid < 32)
                cp_async16(sb + SM_BIAS + ((l + 1) & 1) * 512 + 16 * tid,
                           (const char*)p.B[l + 1] + 16 * tid);
            cp_commit();
        }

        float acc[16][4];
#pragma unroll
        for (int j = 0; j < 16; j++)
#pragma unroll
            for (int q = 0; q < 4; q++) acc[j][q] = 0.0f;

        const uint4* wf = wbuf[cur];
#pragma unroll 1
        for (int ks = 0; ks < K16; ks++) {
#pragma unroll
            for (int j = 0; j < 16; j++) {
                uint4 w = wf[(ks * 16 + j) * 32 + lane];
                mma_fp16(acc[j], af[ks], w.x, w.y);   // A * Bh
                mma_fp16(acc[j], af[ks], w.z, w.w);   // A * Bl
            }
        }

        const float* bs = bias[cur];
        if (l < 6) {
            // bias + relu, repack D -> next-layer A fragments (lane-local)
#pragma unroll
            for (int j = 0; j < 16; j++) {
                float b0 = bs[8 * j + 2 * tc];
                float b1 = bs[8 * j + 2 * tc + 1];
                acc[j][0] = fmaxf(acc[j][0] + b0, 0.0f);
                acc[j][1] = fmaxf(acc[j][1] + b1, 0.0f);
                acc[j][2] = fmaxf(acc[j][2] + b0, 0.0f);
                acc[j][3] = fmaxf(acc[j][3] + b1, 0.0f);
            }
#pragma unroll
            for (int t = 0; t < 8; t++) {
                af[t][0] = cvt_f16x2(acc[2 * t][0],     acc[2 * t][1]);
                af[t][1] = cvt_f16x2(acc[2 * t][2],     acc[2 * t][3]);
                af[t][2] = cvt_f16x2(acc[2 * t + 1][0], acc[2 * t + 1][1]);
                af[t][3] = cvt_f16x2(acc[2 * t + 1][2], acc[2 * t + 1][3]);
            }
        } else {
            float* o0 = out + (size_t)r0 * 128;
            float* o1 = out + (size_t)r1 * 128;
#pragma unroll
            for (int j = 0; j < 16; j++) {
                const int col = 8 * j + 2 * tc;
                float b0 = bs[col], b1 = bs[col + 1];
                float2 v0 = make_float2(acc[j][0] + b0, acc[j][1] + b1);
                float2 v1 = make_float2(acc[j][2] + b0, acc[j][3] + b1);
                *(float2*)(o0 + col) = v0;
                *(float2*)(o1 + col) = v1;
            }
        }
    }
}

// ---------------- launch ----------------
extern "C" void kernel_launch(void* const* d_in, const int* in_sizes, int n_in,
                              void* d_out, int out_size) {
    const float* x    = (const float*)d_in[0];
    const float* g0   = (const float*)d_in[1];
    const float* g1   = (const float*)d_in[2];
    const float* g2   = (const float*)d_in[3];
    const float* g3   = (const float*)d_in[4];
    const float* coef = (const float*)d_in[5];

    MLPW p;
    for (int j = 0; j < 7; j++) {
        p.W[j] = (const float*)d_in[6 + 2 * j];
        p.B[j] = (const float*)d_in[7 + 2 * j];
    }
    float* out = (float*)d_out;

    cudaFuncSetAttribute(mlp_mma, cudaFuncAttributeMaxDynamicSharedMemorySize, SM_DYN);

    void* ptr;
    cudaGetSymbolAddress(&ptr, d_g0t);   float4* g0t = (float4*)ptr;
    cudaGetSymbolAddress(&ptr, d_g1t);   float4* g1t = (float4*)ptr;
    cudaGetSymbolAddress(&ptr, d_g2t);   float4* g2t = (float4*)ptr;
    cudaGetSymbolAddress(&ptr, d_g3t);   float4* g3t = (float4*)ptr;
    cudaGetSymbolAddress(&ptr, d_coeft); float4* ct  = (float4*)ptr;

    transpose_cl<<<(32 * 32 * 32 + 255) / 256, 256>>>(g0, g0t, 32 * 32 * 32);
    transpose_cl<<<(64 * 64 * 64 + 255) / 256, 256>>>(g1, g1t, 64 * 64 * 64);
    transpose_cl<<<(128 * 128 * 128 + 255) / 256, 256>>>(g2, g2t, 128 * 128 * 128);
    transpose_cl<<<(256 * 256 * 256 + 255) / 256, 256>>>(g3, g3t, 256 * 256 * 256);
    transpose_cl<<<(64 * 64 * 64 + 255) / 256, 256>>>(coef, ct, 64 * 64 * 64);

    pack_weights<<<(7 * 8 * 16 * 32 + 255) / 256, 256>>>(p);

    mlp_mma<<<N_PTS / 128, 256, SM_DYN>>>(p, x, out);
}

// round 6
// speedup vs baseline: 3.2102x; 1.1527x over previous
#include <cuda_runtime.h>
#include <cuda_fp16.h>
#include <math.h>
#include <stdint.h>

#define N_PTS 524288

// ---------------- scratch (device globals; no allocation) ----------------
__device__ float4 d_g0t[32 * 32 * 32];
__device__ float4 d_g1t[64 * 64 * 64];
__device__ float4 d_g2t[128 * 128 * 128];
__device__ float4 d_g3t[256 * 256 * 256];
__device__ float4 d_coeft[64 * 64 * 64];
// packed weight fragments: [7 layers][kstep 8][ntile 16][lane 32] x uint4
// uint4 = {Bh.b0, Bh.b1, Bl.b0, Bl.b1} (fp16x2) in mma.m16n8k16 col-B layout.
__device__ __align__(16) unsigned char d_wpack[7 * 65536];

// ================= helpers =================
__device__ __forceinline__ uint32_t smem_to_u32(const void* p) {
    uint32_t a;
    asm("{ .reg .u64 t; cvta.to.shared.u64 t, %1; cvt.u32.u64 %0, t; }"
        : "=r"(a) : "l"(p));
    return a;
}
// pack two f32 -> f16x2 (low half = v0)
__device__ __forceinline__ uint32_t cvt_f16x2(float v0, float v1) {
    uint32_t d;
    asm("cvt.rn.f16x2.f32 %0, %1, %2;" : "=r"(d) : "f"(v1), "f"(v0));
    return d;
}
__device__ __forceinline__ void mma_fp16(float* c, const uint32_t* a,
                                         uint32_t b0, uint32_t b1) {
    asm volatile(
        "mma.sync.aligned.m16n8k16.row.col.f32.f16.f16.f32 "
        "{%0,%1,%2,%3}, {%4,%5,%6,%7}, {%8,%9}, {%0,%1,%2,%3};"
        : "+f"(c[0]), "+f"(c[1]), "+f"(c[2]), "+f"(c[3])
        : "r"(a[0]), "r"(a[1]), "r"(a[2]), "r"(a[3]), "r"(b0), "r"(b1));
}
__device__ __forceinline__ void cp_async16(uint32_t smem_dst, const void* gsrc) {
    asm volatile("cp.async.cg.shared.global [%0], [%1], 16;"
                 :: "r"(smem_dst), "l"(gsrc));
}
__device__ __forceinline__ void cp_commit() {
    asm volatile("cp.async.commit_group;" ::: "memory");
}
__device__ __forceinline__ void cp_wait_all() {
    asm volatile("cp.async.wait_group 0;" ::: "memory");
}

// ---------------- channels-last transpose: [4,V] -> [V] float4 ----------------
__global__ void transpose_cl(const float* __restrict__ src, float4* __restrict__ dst, int V) {
    int v = blockIdx.x * blockDim.x + threadIdx.x;
    if (v < V) {
        dst[v] = make_float4(src[v], src[v + V], src[v + 2 * V], src[v + 3 * V]);
    }
}

// ---------------- weight packer ----------------
struct MLPW {
    const float* W[7];
    const float* B[7];
};

// fragment layout for mma.m16n8k16 row.col, B is [K,128] row-major in memory:
// b0 = {B[k0][n], B[k0+1][n]}, b1 = {B[k0+8][n], B[k0+9][n]},
// k0 = 16*kstep + 2*(lane&3), n = 8*ntile + (lane>>2)
// fp16 split: Bh = fp16(W), Bl = fp16(W - Bh)
__global__ void pack_weights(MLPW p) {
    int t = blockIdx.x * blockDim.x + threadIdx.x;
    if (t >= 7 * 8 * 16 * 32) return;
    int l     = t >> 12;
    int r     = t & 4095;
    int kstep = r >> 9;
    int ntile = (r >> 5) & 15;
    int lane  = r & 31;

    uint4 frag = make_uint4(0, 0, 0, 0);
    if (!(l == 0 && kstep > 0)) {
        int n  = ntile * 8 + (lane >> 2);
        int k0 = kstep * 16 + 2 * (lane & 3);
        const float* W = p.W[l];
        float w00 = W[(k0 + 0) * 128 + n];
        float w01 = W[(k0 + 1) * 128 + n];
        float w08 = W[(k0 + 8) * 128 + n];
        float w09 = W[(k0 + 9) * 128 + n];
        float h00 = __half2float(__float2half_rn(w00));
        float h01 = __half2float(__float2half_rn(w01));
        float h08 = __half2float(__float2half_rn(w08));
        float h09 = __half2float(__float2half_rn(w09));
        frag.x = cvt_f16x2(h00, h01);
        frag.y = cvt_f16x2(h08, h09);
        frag.z = cvt_f16x2(w00 - h00, w01 - h01);
        frag.w = cvt_f16x2(w08 - h08, w09 - h09);
    }
    *(uint4*)(d_wpack + (size_t)l * 65536 + (size_t)r * 16) = frag;
}

// ---------------- trilerp on channels-last grid ----------------
__device__ __forceinline__ float4 trilerp4(const float4* __restrict__ g, int R,
                                           float px, float py, float pz) {
    float s = 0.5f * (float)(R - 1);
    float cx = (px + 1.0f) * s;
    float cy = (py + 1.0f) * s;
    float cz = (pz + 1.0f) * s;
    float fx0 = floorf(cx), fy0 = floorf(cy), fz0 = floorf(cz);
    float fx = cx - fx0, fy = cy - fy0, fz = cz - fz0;
    int x0 = min(max((int)fx0, 0), R - 1);
    int y0 = min(max((int)fy0, 0), R - 1);
    int z0 = min(max((int)fz0, 0), R - 1);
    int x1 = min(x0 + 1, R - 1);
    int y1 = min(y0 + 1, R - 1);
    int z1 = min(z0 + 1, R - 1);

    const float4 v000 = __ldg(&g[(z0 * R + y0) * R + x0]);
    const float4 v001 = __ldg(&g[(z0 * R + y0) * R + x1]);
    const float4 v010 = __ldg(&g[(z0 * R + y1) * R + x0]);
    const float4 v011 = __ldg(&g[(z0 * R + y1) * R + x1]);
    const float4 v100 = __ldg(&g[(z1 * R + y0) * R + x0]);
    const float4 v101 = __ldg(&g[(z1 * R + y0) * R + x1]);
    const float4 v110 = __ldg(&g[(z1 * R + y1) * R + x0]);
    const float4 v111 = __ldg(&g[(z1 * R + y1) * R + x1]);

    float gx = 1.0f - fx, gy = 1.0f - fy, gz = 1.0f - fz;
    float w00 = gz * gy, w01 = gz * fy, w10 = fz * gy, w11 = fz * fy;

    float4 r;
    r.x = (v000.x * gx + v001.x * fx) * w00 + (v010.x * gx + v011.x * fx) * w01
        + (v100.x * gx + v101.x * fx) * w10 + (v110.x * gx + v111.x * fx) * w11;
    r.y = (v000.y * gx + v001.y * fx) * w00 + (v010.y * gx + v011.y * fx) * w01
        + (v100.y * gx + v101.y * fx) * w10 + (v110.y * gx + v111.y * fx) * w11;
    r.z = (v000.z * gx + v001.z * fx) * w00 + (v010.z * gx + v011.z * fx) * w01
        + (v100.z * gx + v101.z * fx) * w10 + (v110.z * gx + v111.z * fx) * w11;
    r.w = (v000.w * gx + v001.w * fx) * w00 + (v010.w * gx + v011.w * fx) * w01
        + (v100.w * gx + v101.w * fx) * w10 + (v110.w * gx + v111.w * fx) * w11;
    return r;
}

__device__ __forceinline__ float fracf(float a) { return a - floorf(a); }

// ---------------- fused encode + tensor-core MLP ----------------
// CTA = 256 threads (8 warps), tile = 128 points, 2 CTAs/SM (co-residency:
// one CTA's gather-bound encode overlaps the other's tensor-bound MLP).
// Single 64KB weight buffer, reloaded per layer from L2 (weights L2-hot);
// the per-layer reload exposure is hidden by the co-resident CTA.
#define SM_WBUF 65536
#define SM_BIAS SM_WBUF
#define SM_FEAT (SM_WBUF + 512)
#define SM_DYN  (SM_FEAT + 16 * 128 * 4)

__global__ void __launch_bounds__(256, 2) mlp_mma(MLPW p, const float* __restrict__ x,
                                                  float* __restrict__ out) {
    extern __shared__ char smem[];
    const int tid  = threadIdx.x;
    const int wid  = tid >> 5;
    const int lane = tid & 31;
    const int g    = lane >> 2;
    const int tc   = lane & 3;
    const int base = blockIdx.x * 128;

    const uint4*  wbuf = (const uint4*)smem;
    const float*  bs   = (const float*)(smem + SM_BIAS);
    float* sfeat = (float*)(smem + SM_FEAT);   // [16][128]
    const uint32_t sb = smem_to_u32(smem);

    // --- issue layer-0 weights (512 frags) + bias; hides under encode ---
    for (int i = tid; i < 512; i += 256)
        cp_async16(sb + 16 * i, d_wpack + 16 * (size_t)i);
    if (tid < 32)
        cp_async16(sb + SM_BIAS + 16 * tid, (const char*)p.B[0] + 16 * tid);
    cp_commit();

    // --- fused encode: 2 threads per point ---
    {
        const int half = tid >> 7;
        const int pl   = tid & 127;
        const int i    = base + pl;
        float px = x[3 * i + 0];
        float py = x[3 * i + 1];
        float pz = x[3 * i + 2];
        float4 coef = trilerp4(d_coeft, 64, px, py, pz);

        if (half == 0) {
            {
                float ex = 2.0f * fracf(px) - 1.0f;
                float ey = 2.0f * fracf(py) - 1.0f;
                float ez = 2.0f * fracf(pz) - 1.0f;
                float4 v = trilerp4(d_g0t, 32, ex, ey, ez);
                sfeat[0 * 128 + pl] = v.x * coef.x;
                sfeat[1 * 128 + pl] = v.y * coef.x;
                sfeat[2 * 128 + pl] = v.z * coef.x;
                sfeat[3 * 128 + pl] = v.w * coef.x;
            }
            {
                float ex = 2.0f * fracf(px * 2.0f) - 1.0f;
                float ey = 2.0f * fracf(py * 2.0f) - 1.0f;
                float ez = 2.0f * fracf(pz * 2.0f) - 1.0f;
                float4 v = trilerp4(d_g1t, 64, ex, ey, ez);
                sfeat[4 * 128 + pl] = v.x * coef.y;
                sfeat[5 * 128 + pl] = v.y * coef.y;
                sfeat[6 * 128 + pl] = v.z * coef.y;
                sfeat[7 * 128 + pl] = v.w * coef.y;
            }
        } else {
            {
                float ex = 2.0f * fracf(px * 4.0f) - 1.0f;
                float ey = 2.0f * fracf(py * 4.0f) - 1.0f;
                float ez = 2.0f * fracf(pz * 4.0f) - 1.0f;
                float4 v = trilerp4(d_g2t, 128, ex, ey, ez);
                sfeat[8 * 128 + pl]  = v.x * coef.z;
                sfeat[9 * 128 + pl]  = v.y * coef.z;
                sfeat[10 * 128 + pl] = v.z * coef.z;
                sfeat[11 * 128 + pl] = v.w * coef.z;
            }
            {
                float ex = 2.0f * fracf(px * 8.0f) - 1.0f;
                float ey = 2.0f * fracf(py * 8.0f) - 1.0f;
                float ez = 2.0f * fracf(pz * 8.0f) - 1.0f;
                float4 v = trilerp4(d_g3t, 256, ex, ey, ez);
                sfeat[12 * 128 + pl] = v.x * coef.w;
                sfeat[13 * 128 + pl] = v.y * coef.w;
                sfeat[14 * 128 + pl] = v.z * coef.w;
                sfeat[15 * 128 + pl] = v.w * coef.w;
            }
        }
    }
    __syncthreads();

    // --- layer-0 A fragments (single fp16), kstep 0 only ---
    uint32_t af[8][4];
    {
        const int k0  = 2 * tc;
        const int rl0 = wid * 16 + g;
        const int rl1 = rl0 + 8;
        af[0][0] = cvt_f16x2(sfeat[(k0 + 0) * 128 + rl0], sfeat[(k0 + 1) * 128 + rl0]);
        af[0][1] = cvt_f16x2(sfeat[(k0 + 0) * 128 + rl1], sfeat[(k0 + 1) * 128 + rl1]);
        af[0][2] = cvt_f16x2(sfeat[(k0 + 8) * 128 + rl0], sfeat[(k0 + 9) * 128 + rl0]);
        af[0][3] = cvt_f16x2(sfeat[(k0 + 8) * 128 + rl1], sfeat[(k0 + 9) * 128 + rl1]);
    }

    const int r0 = base + wid * 16 + g;
    const int r1 = r0 + 8;

    // weights for layer 0 ready?
    cp_wait_all();
    __syncthreads();

    for (int l = 0; l < 7; l++) {
        const int K16 = (l == 0) ? 1 : 8;

        float acc[16][4];
#pragma unroll
        for (int j = 0; j < 16; j++)
#pragma unroll
            for (int q = 0; q < 4; q++) acc[j][q] = 0.0f;

#pragma unroll 1
        for (int ks = 0; ks < K16; ks++) {
#pragma unroll
            for (int j = 0; j < 16; j++) {
                uint4 w = wbuf[(ks * 16 + j) * 32 + lane];
                mma_fp16(acc[j], af[ks], w.x, w.y);   // A * Bh
                mma_fp16(acc[j], af[ks], w.z, w.w);   // A * Bl
            }
        }

        if (l < 6) {
            // bias + relu, repack D -> next-layer A fragments (lane-local)
#pragma unroll
            for (int j = 0; j < 16; j++) {
                float b0 = bs[8 * j + 2 * tc];
                float b1 = bs[8 * j + 2 * tc + 1];
                acc[j][0] = fmaxf(acc[j][0] + b0, 0.0f);
                acc[j][1] = fmaxf(acc[j][1] + b1, 0.0f);
                acc[j][2] = fmaxf(acc[j][2] + b0, 0.0f);
                acc[j][3] = fmaxf(acc[j][3] + b1, 0.0f);
            }
#pragma unroll
            for (int t = 0; t < 8; t++) {
                af[t][0] = cvt_f16x2(acc[2 * t][0],     acc[2 * t][1]);
                af[t][1] = cvt_f16x2(acc[2 * t][2],     acc[2 * t][3]);
                af[t][2] = cvt_f16x2(acc[2 * t + 1][0], acc[2 * t + 1][1]);
                af[t][3] = cvt_f16x2(acc[2 * t + 1][2], acc[2 * t + 1][3]);
            }

            // all warps done reading wbuf/bias of layer l -> reload for l+1
            __syncthreads();
            {
                const char* src = (const char*)(d_wpack + (size_t)(l + 1) * 65536);
                for (int i = tid; i < 4096; i += 256)
                    cp_async16(sb + 16 * i, src + 16 * (size_t)i);
                if (tid < 32)
                    cp_async16(sb + SM_BIAS + 16 * tid,
                               (const char*)p.B[l + 1] + 16 * tid);
                cp_commit();
            }
            cp_wait_all();
            __syncthreads();
        } else {
            float* o0 = out + (size_t)r0 * 128;
            float* o1 = out + (size_t)r1 * 128;
#pragma unroll
            for (int j = 0; j < 16; j++) {
                const int col = 8 * j + 2 * tc;
                float b0 = bs[col], b1 = bs[col + 1];
                float2 v0 = make_float2(acc[j][0] + b0, acc[j][1] + b1);
                float2 v1 = make_float2(acc[j][2] + b0, acc[j][3] + b1);
                *(float2*)(o0 + col) = v0;
                *(float2*)(o1 + col) = v1;
            }
        }
    }
}

// ---------------- launch ----------------
extern "C" void kernel_launch(void* const* d_in, const int* in_sizes, int n_in,
                              void* d_out, int out_size) {
    const float* x    = (const float*)d_in[0];
    const float* g0   = (const float*)d_in[1];
    const float* g1   = (const float*)d_in[2];
    const float* g2   = (const float*)d_in[3];
    const float* g3   = (const float*)d_in[4];
    const float* coef = (const float*)d_in[5];

    MLPW p;
    for (int j = 0; j < 7; j++) {
        p.W[j] = (const float*)d_in[6 + 2 * j];
        p.B[j] = (const float*)d_in[7 + 2 * j];
    }
    float* out = (float*)d_out;

    cudaFuncSetAttribute(mlp_mma, cudaFuncAttributeMaxDynamicSharedMemorySize, SM_DYN);

    void* ptr;
    cudaGetSymbolAddress(&ptr, d_g0t);   float4* g0t = (float4*)ptr;
    cudaGetSymbolAddress(&ptr, d_g1t);   float4* g1t = (float4*)ptr;
    cudaGetSymbolAddress(&ptr, d_g2t);   float4* g2t = (float4*)ptr;
    cudaGetSymbolAddress(&ptr, d_g3t);   float4* g3t = (float4*)ptr;
    cudaGetSymbolAddress(&ptr, d_coeft); float4* ct  = (float4*)ptr;

    transpose_cl<<<(32 * 32 * 32 + 255) / 256, 256>>>(g0, g0t, 32 * 32 * 32);
    transpose_cl<<<(64 * 64 * 64 + 255) / 256, 256>>>(g1, g1t, 64 * 64 * 64);
    transpose_cl<<<(128 * 128 * 128 + 255) / 256, 256>>>(g2, g2t, 128 * 128 * 128);
    transpose_cl<<<(256 * 256 * 256 + 255) / 256, 256>>>(g3, g3t, 256 * 256 * 256);
    transpose_cl<<<(64 * 64 * 64 + 255) / 256, 256>>>(coef, ct, 64 * 64 * 64);

    pack_weights<<<(7 * 8 * 16 * 32 + 255) / 256, 256>>>(p);

    mlp_mma<<<N_PTS / 128, 256, SM_DYN>>>(p, x, out);
}

// round 7
// speedup vs baseline: 3.2725x; 1.0194x over previous
#include <cuda_runtime.h>
#include <cuda_fp16.h>
#include <math.h>
#include <stdint.h>

#define N_PTS 524288

// ---------------- scratch (device globals; no allocation) ----------------
__device__ float4 d_g0t[32 * 32 * 32];
__device__ float4 d_g1t[64 * 64 * 64];
__device__ float4 d_g2t[128 * 128 * 128];
__device__ float4 d_g3t[256 * 256 * 256];
__device__ float4 d_coeft[64 * 64 * 64];
// packed weight fragments: [7 layers][kstep 8][ntile 16][lane 32] x uint2
// uint2 = {B.b0, B.b1} (fp16x2) in mma.m16n8k16 col-B fragment layout.
__device__ __align__(16) unsigned char d_wpack[7 * 32768];

// ================= helpers =================
__device__ __forceinline__ uint32_t smem_to_u32(const void* p) {
    uint32_t a;
    asm("{ .reg .u64 t; cvta.to.shared.u64 t, %1; cvt.u32.u64 %0, t; }"
        : "=r"(a) : "l"(p));
    return a;
}
// pack two f32 -> f16x2 (low half = v0)
__device__ __forceinline__ uint32_t cvt_f16x2(float v0, float v1) {
    uint32_t d;
    asm("cvt.rn.f16x2.f32 %0, %1, %2;" : "=r"(d) : "f"(v1), "f"(v0));
    return d;
}
__device__ __forceinline__ void mma_fp16(float* c, const uint32_t* a,
                                         uint32_t b0, uint32_t b1) {
    asm volatile(
        "mma.sync.aligned.m16n8k16.row.col.f32.f16.f16.f32 "
        "{%0,%1,%2,%3}, {%4,%5,%6,%7}, {%8,%9}, {%0,%1,%2,%3};"
        : "+f"(c[0]), "+f"(c[1]), "+f"(c[2]), "+f"(c[3])
        : "r"(a[0]), "r"(a[1]), "r"(a[2]), "r"(a[3]), "r"(b0), "r"(b1));
}
__device__ __forceinline__ void cp_async16(uint32_t smem_dst, const void* gsrc) {
    asm volatile("cp.async.cg.shared.global [%0], [%1], 16;"
                 :: "r"(smem_dst), "l"(gsrc));
}
__device__ __forceinline__ void cp_commit() {
    asm volatile("cp.async.commit_group;" ::: "memory");
}
__device__ __forceinline__ void cp_wait_all() {
    asm volatile("cp.async.wait_group 0;" ::: "memory");
}

// ---------------- fused channels-last transposes: [4,V] -> [V] float4 ----------------
struct TP {
    const float* src[5];
    float4* dst[5];
    int V[5];
};
__global__ void transpose_cl5(TP p) {
    int v = blockIdx.x * blockDim.x + threadIdx.x;
#pragma unroll
    for (int s = 0; s < 5; s++) {
        int Vs = p.V[s];
        if (v < Vs) {
            const float* src = p.src[s];
            p.dst[s][v] = make_float4(src[v], src[v + Vs], src[v + 2 * Vs], src[v + 3 * Vs]);
            return;
        }
        v -= Vs;
    }
}

// ---------------- weight packer ----------------
struct MLPW {
    const float* W[7];
    const float* B[7];
};

// fragment layout for mma.m16n8k16 row.col, B is [K,128] row-major in memory:
// b0 = {B[k0][n], B[k0+1][n]}, b1 = {B[k0+8][n], B[k0+9][n]},
// k0 = 16*kstep + 2*(lane&3), n = 8*ntile + (lane>>2). Single fp16.
__global__ void pack_weights(MLPW p) {
    int t = blockIdx.x * blockDim.x + threadIdx.x;
    if (t >= 7 * 8 * 16 * 32) return;
    int l     = t >> 12;
    int r     = t & 4095;
    int kstep = r >> 9;
    int ntile = (r >> 5) & 15;
    int lane  = r & 31;

    uint2 frag = make_uint2(0, 0);
    if (!(l == 0 && kstep > 0)) {
        int n  = ntile * 8 + (lane >> 2);
        int k0 = kstep * 16 + 2 * (lane & 3);
        const float* W = p.W[l];
        frag.x = cvt_f16x2(W[(k0 + 0) * 128 + n], W[(k0 + 1) * 128 + n]);
        frag.y = cvt_f16x2(W[(k0 + 8) * 128 + n], W[(k0 + 9) * 128 + n]);
    }
    *(uint2*)(d_wpack + (size_t)l * 32768 + (size_t)r * 8) = frag;
}

// ---------------- trilerp on channels-last grid ----------------
__device__ __forceinline__ float4 trilerp4(const float4* __restrict__ g, int R,
                                           float px, float py, float pz) {
    float s = 0.5f * (float)(R - 1);
    float cx = (px + 1.0f) * s;
    float cy = (py + 1.0f) * s;
    float cz = (pz + 1.0f) * s;
    float fx0 = floorf(cx), fy0 = floorf(cy), fz0 = floorf(cz);
    float fx = cx - fx0, fy = cy - fy0, fz = cz - fz0;
    int x0 = min(max((int)fx0, 0), R - 1);
    int y0 = min(max((int)fy0, 0), R - 1);
    int z0 = min(max((int)fz0, 0), R - 1);
    int x1 = min(x0 + 1, R - 1);
    int y1 = min(y0 + 1, R - 1);
    int z1 = min(z0 + 1, R - 1);

    const float4 v000 = __ldg(&g[(z0 * R + y0) * R + x0]);
    const float4 v001 = __ldg(&g[(z0 * R + y0) * R + x1]);
    const float4 v010 = __ldg(&g[(z0 * R + y1) * R + x0]);
    const float4 v011 = __ldg(&g[(z0 * R + y1) * R + x1]);
    const float4 v100 = __ldg(&g[(z1 * R + y0) * R + x0]);
    const float4 v101 = __ldg(&g[(z1 * R + y0) * R + x1]);
    const float4 v110 = __ldg(&g[(z1 * R + y1) * R + x0]);
    const float4 v111 = __ldg(&g[(z1 * R + y1) * R + x1]);

    float gx = 1.0f - fx, gy = 1.0f - fy, gz = 1.0f - fz;
    float w00 = gz * gy, w01 = gz * fy, w10 = fz * gy, w11 = fz * fy;

    float4 r;
    r.x = (v000.x * gx + v001.x * fx) * w00 + (v010.x * gx + v011.x * fx) * w01
        + (v100.x * gx + v101.x * fx) * w10 + (v110.x * gx + v111.x * fx) * w11;
    r.y = (v000.y * gx + v001.y * fx) * w00 + (v010.y * gx + v011.y * fx) * w01
        + (v100.y * gx + v101.y * fx) * w10 + (v110.y * gx + v111.y * fx) * w11;
    r.z = (v000.z * gx + v001.z * fx) * w00 + (v010.z * gx + v011.z * fx) * w01
        + (v100.z * gx + v101.z * fx) * w10 + (v110.z * gx + v111.z * fx) * w11;
    r.w = (v000.w * gx + v001.w * fx) * w00 + (v010.w * gx + v011.w * fx) * w01
        + (v100.w * gx + v101.w * fx) * w10 + (v110.w * gx + v111.w * fx) * w11;
    return r;
}

__device__ __forceinline__ float fracf(float a) { return a - floorf(a); }

// ---------------- fused encode + tensor-core MLP ----------------
// CTA = 256 threads (8 warps), tile = 128 points, 2 CTAs/SM.
// Double-buffered 32KB weight buffers (cp.async) -> no reload exposure;
// single-fp16 weights: 1 MMA per (kstep,j), uint2 fragments (halved LDS).
#define SM_WBUF 32768
#define SM_BIAS (2 * SM_WBUF)
#define SM_FEAT (SM_BIAS + 2 * 512)
#define SM_DYN  (SM_FEAT + 16 * 128 * 4)

__global__ void __launch_bounds__(256, 2) mlp_mma(MLPW p, const float* __restrict__ x,
                                                  float* __restrict__ out) {
    extern __shared__ char smem[];
    const int tid  = threadIdx.x;
    const int wid  = tid >> 5;
    const int lane = tid & 31;
    const int g    = lane >> 2;
    const int tc   = lane & 3;
    const int base = blockIdx.x * 128;

    const uint2* wbuf[2] = {(const uint2*)smem, (const uint2*)(smem + SM_WBUF)};
    const float* bias[2] = {(const float*)(smem + SM_BIAS),
                            (const float*)(smem + SM_BIAS + 512)};
    float* sfeat = (float*)(smem + SM_FEAT);   // [16][128]
    const uint32_t sb = smem_to_u32(smem);

    // --- prefetch layer-0 weights (32KB = 2048 uint4) + bias; hides under encode ---
    for (int i = tid; i < 2048; i += 256)
        cp_async16(sb + 16 * i, d_wpack + 16 * (size_t)i);
    if (tid < 32)
        cp_async16(sb + SM_BIAS + 16 * tid, (const char*)p.B[0] + 16 * tid);
    cp_commit();

    // --- fused encode: 2 threads per point ---
    {
        const int half = tid >> 7;
        const int pl   = tid & 127;
        const int i    = base + pl;
        float px = x[3 * i + 0];
        float py = x[3 * i + 1];
        float pz = x[3 * i + 2];
        float4 coef = trilerp4(d_coeft, 64, px, py, pz);

        if (half == 0) {
            {
                float ex = 2.0f * fracf(px) - 1.0f;
                float ey = 2.0f * fracf(py) - 1.0f;
                float ez = 2.0f * fracf(pz) - 1.0f;
                float4 v = trilerp4(d_g0t, 32, ex, ey, ez);
                sfeat[0 * 128 + pl] = v.x * coef.x;
                sfeat[1 * 128 + pl] = v.y * coef.x;
                sfeat[2 * 128 + pl] = v.z * coef.x;
                sfeat[3 * 128 + pl] = v.w * coef.x;
            }
            {
                float ex = 2.0f * fracf(px * 2.0f) - 1.0f;
                float ey = 2.0f * fracf(py * 2.0f) - 1.0f;
                float ez = 2.0f * fracf(pz * 2.0f) - 1.0f;
                float4 v = trilerp4(d_g1t, 64, ex, ey, ez);
                sfeat[4 * 128 + pl] = v.x * coef.y;
                sfeat[5 * 128 + pl] = v.y * coef.y;
                sfeat[6 * 128 + pl] = v.z * coef.y;
                sfeat[7 * 128 + pl] = v.w * coef.y;
            }
        } else {
            {
                float ex = 2.0f * fracf(px * 4.0f) - 1.0f;
                float ey = 2.0f * fracf(py * 4.0f) - 1.0f;
                float ez = 2.0f * fracf(pz * 4.0f) - 1.0f;
                float4 v = trilerp4(d_g2t, 128, ex, ey, ez);
                sfeat[8 * 128 + pl]  = v.x * coef.z;
                sfeat[9 * 128 + pl]  = v.y * coef.z;
                sfeat[10 * 128 + pl] = v.z * coef.z;
                sfeat[11 * 128 + pl] = v.w * coef.z;
            }
            {
                float ex = 2.0f * fracf(px * 8.0f) - 1.0f;
                float ey = 2.0f * fracf(py * 8.0f) - 1.0f;
                float ez = 2.0f * fracf(pz * 8.0f) - 1.0f;
                float4 v = trilerp4(d_g3t, 256, ex, ey, ez);
                sfeat[12 * 128 + pl] = v.x * coef.w;
                sfeat[13 * 128 + pl] = v.y * coef.w;
                sfeat[14 * 128 + pl] = v.z * coef.w;
                sfeat[15 * 128 + pl] = v.w * coef.w;
            }
        }
    }
    __syncthreads();

    // --- layer-0 A fragments (single fp16), kstep 0 only ---
    uint32_t af[8][4];
    {
        const int k0  = 2 * tc;
        const int rl0 = wid * 16 + g;
        const int rl1 = rl0 + 8;
        af[0][0] = cvt_f16x2(sfeat[(k0 + 0) * 128 + rl0], sfeat[(k0 + 1) * 128 + rl0]);
        af[0][1] = cvt_f16x2(sfeat[(k0 + 0) * 128 + rl1], sfeat[(k0 + 1) * 128 + rl1]);
        af[0][2] = cvt_f16x2(sfeat[(k0 + 8) * 128 + rl0], sfeat[(k0 + 9) * 128 + rl0]);
        af[0][3] = cvt_f16x2(sfeat[(k0 + 8) * 128 + rl1], sfeat[(k0 + 9) * 128 + rl1]);
    }

    const int r0 = base + wid * 16 + g;
    const int r1 = r0 + 8;

    for (int l = 0; l < 7; l++) {
        const int K16 = (l == 0) ? 1 : 8;
        const int cur = l & 1;

        // weights for layer l ready
        cp_wait_all();
        __syncthreads();

        // kick off next layer's weights + bias into the other buffer;
        // the copy overlaps this layer's MMAs.
        if (l < 6) {
            const char* src = (const char*)(d_wpack + (size_t)(l + 1) * 32768);
            uint32_t dst = sb + ((l + 1) & 1) * SM_WBUF;
            for (int i = tid; i < 2048; i += 256)
                cp_async16(dst + 16 * i, src + 16 * (size_t)i);
            if (tid < 32)
                cp_async16(sb + SM_BIAS + ((l + 1) & 1) * 512 + 16 * tid,
                           (const char*)p.B[l + 1] + 16 * tid);
            cp_commit();
        }

        float acc[16][4];
#pragma unroll
        for (int j = 0; j < 16; j++)
#pragma unroll
            for (int q = 0; q < 4; q++) acc[j][q] = 0.0f;

        const uint2* wf = wbuf[cur];
#pragma unroll 1
        for (int ks = 0; ks < K16; ks++) {
#pragma unroll
            for (int j = 0; j < 16; j++) {
                uint2 w = wf[(ks * 16 + j) * 32 + lane];
                mma_fp16(acc[j], af[ks], w.x, w.y);
            }
        }

        const float* bs = bias[cur];
        if (l < 6) {
            // bias + relu, repack D -> next-layer A fragments (lane-local)
#pragma unroll
            for (int j = 0; j < 16; j++) {
                float b0 = bs[8 * j + 2 * tc];
                float b1 = bs[8 * j + 2 * tc + 1];
                acc[j][0] = fmaxf(acc[j][0] + b0, 0.0f);
                acc[j][1] = fmaxf(acc[j][1] + b1, 0.0f);
                acc[j][2] = fmaxf(acc[j][2] + b0, 0.0f);
                acc[j][3] = fmaxf(acc[j][3] + b1, 0.0f);
            }
#pragma unroll
            for (int t = 0; t < 8; t++) {
                af[t][0] = cvt_f16x2(acc[2 * t][0],     acc[2 * t][1]);
                af[t][1] = cvt_f16x2(acc[2 * t][2],     acc[2 * t][3]);
                af[t][2] = cvt_f16x2(acc[2 * t + 1][0], acc[2 * t + 1][1]);
                af[t][3] = cvt_f16x2(acc[2 * t + 1][2], acc[2 * t + 1][3]);
            }
        } else {
            float* o0 = out + (size_t)r0 * 128;
            float* o1 = out + (size_t)r1 * 128;
#pragma unroll
            for (int j = 0; j < 16; j++) {
                const int col = 8 * j + 2 * tc;
                float b0 = bs[col], b1 = bs[col + 1];
                float2 v0 = make_float2(acc[j][0] + b0, acc[j][1] + b1);
                float2 v1 = make_float2(acc[j][2] + b0, acc[j][3] + b1);
                *(float2*)(o0 + col) = v0;
                *(float2*)(o1 + col) = v1;
            }
        }
    }
}

// ---------------- launch ----------------
extern "C" void kernel_launch(void* const* d_in, const int* in_sizes, int n_in,
                              void* d_out, int out_size) {
    const float* x    = (const float*)d_in[0];
    const float* g0   = (const float*)d_in[1];
    const float* g1   = (const float*)d_in[2];
    const float* g2   = (const float*)d_in[3];
    const float* g3   = (const float*)d_in[4];
    const float* coef = (const float*)d_in[5];

    MLPW p;
    for (int j = 0; j < 7; j++) {
        p.W[j] = (const float*)d_in[6 + 2 * j];
        p.B[j] = (const float*)d_in[7 + 2 * j];
    }
    float* out = (float*)d_out;

    cudaFuncSetAttribute(mlp_mma, cudaFuncAttributeMaxDynamicSharedMemorySize, SM_DYN);

    void* ptr;
    TP tp;
    cudaGetSymbolAddress(&ptr, d_g0t);   tp.dst[0] = (float4*)ptr;
    cudaGetSymbolAddress(&ptr, d_g1t);   tp.dst[1] = (float4*)ptr;
    cudaGetSymbolAddress(&ptr, d_g2t);   tp.dst[2] = (float4*)ptr;
    cudaGetSymbolAddress(&ptr, d_g3t);   tp.dst[3] = (float4*)ptr;
    cudaGetSymbolAddress(&ptr, d_coeft); tp.dst[4] = (float4*)ptr;
    tp.src[0] = g0;  tp.V[0] = 32 * 32 * 32;
    tp.src[1] = g1;  tp.V[1] = 64 * 64 * 64;
    tp.src[2] = g2;  tp.V[2] = 128 * 128 * 128;
    tp.src[3] = g3;  tp.V[3] = 256 * 256 * 256;
    tp.src[4] = coef; tp.V[4] = 64 * 64 * 64;
    int totalV = tp.V[0] + tp.V[1] + tp.V[2] + tp.V[3] + tp.V[4];

    transpose_cl5<<<(totalV + 255) / 256, 256>>>(tp);

    pack_weights<<<(7 * 8 * 16 * 32 + 255) / 256, 256>>>(p);

    mlp_mma<<<N_PTS / 128, 256, SM_DYN>>>(p, x, out);
}

// round 8
// speedup vs baseline: 4.2171x; 1.2886x over previous
#include <cuda_runtime.h>
#include <cuda_fp16.h>
#include <math.h>
#include <stdint.h>

#define N_PTS 524288

// ---------------- scratch (device globals; no allocation) ----------------
__device__ float4 d_g0t[32 * 32 * 32];
__device__ float4 d_g1t[64 * 64 * 64];
__device__ float4 d_g2t[128 * 128 * 128];
__device__ float4 d_g3t[256 * 256 * 256];
__device__ float4 d_coeft[64 * 64 * 64];
// packed weight fragments: [7 layers][kstep 8][jpair 8][lane 32] x uint4
// uint4 = {B(j).b0, B(j).b1, B(j+1).b0, B(j+1).b1} (fp16x2 each),
// mma.m16n8k16 col-B fragment layout, j = 2*jpair.
__device__ __align__(16) unsigned char d_wpack[7 * 32768];

// ================= helpers =================
__device__ __forceinline__ uint32_t smem_to_u32(const void* p) {
    uint32_t a;
    asm("{ .reg .u64 t; cvta.to.shared.u64 t, %1; cvt.u32.u64 %0, t; }"
        : "=r"(a) : "l"(p));
    return a;
}
// pack two f32 -> f16x2 (low half = v0)
__device__ __forceinline__ uint32_t cvt_f16x2(float v0, float v1) {
    uint32_t d;
    asm("cvt.rn.f16x2.f32 %0, %1, %2;" : "=r"(d) : "f"(v1), "f"(v0));
    return d;
}
__device__ __forceinline__ void mma_fp16(float* c, const uint32_t* a,
                                         uint32_t b0, uint32_t b1) {
    asm volatile(
        "mma.sync.aligned.m16n8k16.row.col.f32.f16.f16.f32 "
        "{%0,%1,%2,%3}, {%4,%5,%6,%7}, {%8,%9}, {%0,%1,%2,%3};"
        : "+f"(c[0]), "+f"(c[1]), "+f"(c[2]), "+f"(c[3])
        : "r"(a[0]), "r"(a[1]), "r"(a[2]), "r"(a[3]), "r"(b0), "r"(b1));
}
__device__ __forceinline__ void cp_async16(uint32_t smem_dst, const void* gsrc) {
    asm volatile("cp.async.cg.shared.global [%0], [%1], 16;"
                 :: "r"(smem_dst), "l"(gsrc));
}
__device__ __forceinline__ void cp_commit() {
    asm volatile("cp.async.commit_group;" ::: "memory");
}
__device__ __forceinline__ void cp_wait_all() {
    asm volatile("cp.async.wait_group 0;" ::: "memory");
}

// ---------------- channels-last transpose: [4,V] -> [V] float4 ----------------
// (separate launches; compile-time pointer args, no local-memory indexing)
__global__ void transpose_cl(const float* __restrict__ src, float4* __restrict__ dst, int V) {
    int v = blockIdx.x * blockDim.x + threadIdx.x;
    if (v < V) {
        dst[v] = make_float4(src[v], src[v + V], src[v + 2 * V], src[v + 3 * V]);
    }
}

// ---------------- weight packer ----------------
struct MLPW {
    const float* W[7];
    const float* B[7];
};

// fragment layout for mma.m16n8k16 row.col, B is [K,128] row-major in memory:
// b0 = {B[k0][n], B[k0+1][n]}, b1 = {B[k0+8][n], B[k0+9][n]},
// k0 = 16*kstep + 2*(lane&3), n = 8*ntile + (lane>>2). Single fp16.
// Paired storage: fragments for ntile=2*jp and 2*jp+1 adjacent in one uint4.
__global__ void pack_weights(MLPW p) {
    int t = blockIdx.x * blockDim.x + threadIdx.x;
    if (t >= 7 * 8 * 16 * 32) return;
    int l     = t >> 12;
    int r     = t & 4095;
    int kstep = r >> 9;
    int ntile = (r >> 5) & 15;
    int lane  = r & 31;

    uint2 frag = make_uint2(0, 0);
    if (!(l == 0 && kstep > 0)) {
        int n  = ntile * 8 + (lane >> 2);
        int k0 = kstep * 16 + 2 * (lane & 3);
        const float* W = p.W[l];
        frag.x = cvt_f16x2(W[(k0 + 0) * 128 + n], W[(k0 + 1) * 128 + n]);
        frag.y = cvt_f16x2(W[(k0 + 8) * 128 + n], W[(k0 + 9) * 128 + n]);
    }
    int jp   = ntile >> 1;
    int half = ntile & 1;
    size_t off = (size_t)l * 32768 + (((size_t)(kstep * 8 + jp) * 32 + lane) * 16) + half * 8;
    *(uint2*)(d_wpack + off) = frag;
}

// ---------------- trilerp on channels-last grid ----------------
__device__ __forceinline__ float4 trilerp4(const float4* __restrict__ g, int R,
                                           float px, float py, float pz) {
    float s = 0.5f * (float)(R - 1);
    float cx = (px + 1.0f) * s;
    float cy = (py + 1.0f) * s;
    float cz = (pz + 1.0f) * s;
    float fx0 = floorf(cx), fy0 = floorf(cy), fz0 = floorf(cz);
    float fx = cx - fx0, fy = cy - fy0, fz = cz - fz0;
    int x0 = min(max((int)fx0, 0), R - 1);
    int y0 = min(max((int)fy0, 0), R - 1);
    int z0 = min(max((int)fz0, 0), R - 1);
    int x1 = min(x0 + 1, R - 1);
    int y1 = min(y0 + 1, R - 1);
    int z1 = min(z0 + 1, R - 1);

    const float4 v000 = __ldg(&g[(z0 * R + y0) * R + x0]);
    const float4 v001 = __ldg(&g[(z0 * R + y0) * R + x1]);
    const float4 v010 = __ldg(&g[(z0 * R + y1) * R + x0]);
    const float4 v011 = __ldg(&g[(z0 * R + y1) * R + x1]);
    const float4 v100 = __ldg(&g[(z1 * R + y0) * R + x0]);
    const float4 v101 = __ldg(&g[(z1 * R + y0) * R + x1]);
    const float4 v110 = __ldg(&g[(z1 * R + y1) * R + x0]);
    const float4 v111 = __ldg(&g[(z1 * R + y1) * R + x1]);

    float gx = 1.0f - fx, gy = 1.0f - fy, gz = 1.0f - fz;
    float w00 = gz * gy, w01 = gz * fy, w10 = fz * gy, w11 = fz * fy;

    float4 r;
    r.x = (v000.x * gx + v001.x * fx) * w00 + (v010.x * gx + v011.x * fx) * w01
        + (v100.x * gx + v101.x * fx) * w10 + (v110.x * gx + v111.x * fx) * w11;
    r.y = (v000.y * gx + v001.y * fx) * w00 + (v010.y * gx + v011.y * fx) * w01
        + (v100.y * gx + v101.y * fx) * w10 + (v110.y * gx + v111.y * fx) * w11;
    r.z = (v000.z * gx + v001.z * fx) * w00 + (v010.z * gx + v011.z * fx) * w01
        + (v100.z * gx + v101.z * fx) * w10 + (v110.z * gx + v111.z * fx) * w11;
    r.w = (v000.w * gx + v001.w * fx) * w00 + (v010.w * gx + v011.w * fx) * w01
        + (v100.w * gx + v101.w * fx) * w10 + (v110.w * gx + v111.w * fx) * w11;
    return r;
}

__device__ __forceinline__ float fracf(float a) { return a - floorf(a); }

// ---------------- fused encode + tensor-core MLP ----------------
// CTA = 256 threads (8 warps), tile = 128 points, 2 CTAs/SM.
// Double-buffered 32KB weight buffers (cp.async); single-fp16 weights.
// Weight fragments paired: 1 LDS.128 feeds 2 MMAs.
#define SM_WBUF 32768
#define SM_BIAS (2 * SM_WBUF)
#define SM_FEAT (SM_BIAS + 2 * 512)
#define SM_DYN  (SM_FEAT + 16 * 128 * 4)

__global__ void __launch_bounds__(256, 2) mlp_mma(MLPW p, const float* __restrict__ x,
                                                  float* __restrict__ out) {
    extern __shared__ char smem[];
    const int tid  = threadIdx.x;
    const int wid  = tid >> 5;
    const int lane = tid & 31;
    const int g    = lane >> 2;
    const int tc   = lane & 3;
    const int base = blockIdx.x * 128;

    const uint4* wbuf[2] = {(const uint4*)smem, (const uint4*)(smem + SM_WBUF)};
    const float* bias[2] = {(const float*)(smem + SM_BIAS),
                            (const float*)(smem + SM_BIAS + 512)};
    float* sfeat = (float*)(smem + SM_FEAT);   // [16][128]
    const uint32_t sb = smem_to_u32(smem);

    // --- prefetch layer-0 weights (32KB = 2048 x 16B) + bias; hides under encode ---
    for (int i = tid; i < 2048; i += 256)
        cp_async16(sb + 16 * i, d_wpack + 16 * (size_t)i);
    if (tid < 32)
        cp_async16(sb + SM_BIAS + 16 * tid, (const char*)p.B[0] + 16 * tid);
    cp_commit();

    // --- fused encode: 2 threads per point ---
    {
        const int half = tid >> 7;
        const int pl   = tid & 127;
        const int i    = base + pl;
        float px = x[3 * i + 0];
        float py = x[3 * i + 1];
        float pz = x[3 * i + 2];
        float4 coef = trilerp4(d_coeft, 64, px, py, pz);

        if (half == 0) {
            {
                float ex = 2.0f * fracf(px) - 1.0f;
                float ey = 2.0f * fracf(py) - 1.0f;
                float ez = 2.0f * fracf(pz) - 1.0f;
                float4 v = trilerp4(d_g0t, 32, ex, ey, ez);
                sfeat[0 * 128 + pl] = v.x * coef.x;
                sfeat[1 * 128 + pl] = v.y * coef.x;
                sfeat[2 * 128 + pl] = v.z * coef.x;
                sfeat[3 * 128 + pl] = v.w * coef.x;
            }
            {
                float ex = 2.0f * fracf(px * 2.0f) - 1.0f;
                float ey = 2.0f * fracf(py * 2.0f) - 1.0f;
                float ez = 2.0f * fracf(pz * 2.0f) - 1.0f;
                float4 v = trilerp4(d_g1t, 64, ex, ey, ez);
                sfeat[4 * 128 + pl] = v.x * coef.y;
                sfeat[5 * 128 + pl] = v.y * coef.y;
                sfeat[6 * 128 + pl] = v.z * coef.y;
                sfeat[7 * 128 + pl] = v.w * coef.y;
            }
        } else {
            {
                float ex = 2.0f * fracf(px * 4.0f) - 1.0f;
                float ey = 2.0f * fracf(py * 4.0f) - 1.0f;
                float ez = 2.0f * fracf(pz * 4.0f) - 1.0f;
                float4 v = trilerp4(d_g2t, 128, ex, ey, ez);
                sfeat[8 * 128 + pl]  = v.x * coef.z;
                sfeat[9 * 128 + pl]  = v.y * coef.z;
                sfeat[10 * 128 + pl] = v.z * coef.z;
                sfeat[11 * 128 + pl] = v.w * coef.z;
            }
            {
                float ex = 2.0f * fracf(px * 8.0f) - 1.0f;
                float ey = 2.0f * fracf(py * 8.0f) - 1.0f;
                float ez = 2.0f * fracf(pz * 8.0f) - 1.0f;
                float4 v = trilerp4(d_g3t, 256, ex, ey, ez);
                sfeat[12 * 128 + pl] = v.x * coef.w;
                sfeat[13 * 128 + pl] = v.y * coef.w;
                sfeat[14 * 128 + pl] = v.z * coef.w;
                sfeat[15 * 128 + pl] = v.w * coef.w;
            }
        }
    }
    __syncthreads();

    // --- layer-0 A fragments (single fp16), kstep 0 only ---
    uint32_t af[8][4];
    {
        const int k0  = 2 * tc;
        const int rl0 = wid * 16 + g;
        const int rl1 = rl0 + 8;
        af[0][0] = cvt_f16x2(sfeat[(k0 + 0) * 128 + rl0], sfeat[(k0 + 1) * 128 + rl0]);
        af[0][1] = cvt_f16x2(sfeat[(k0 + 0) * 128 + rl1], sfeat[(k0 + 1) * 128 + rl1]);
        af[0][2] = cvt_f16x2(sfeat[(k0 + 8) * 128 + rl0], sfeat[(k0 + 9) * 128 + rl0]);
        af[0][3] = cvt_f16x2(sfeat[(k0 + 8) * 128 + rl1], sfeat[(k0 + 9) * 128 + rl1]);
    }

    const int r0 = base + wid * 16 + g;
    const int r1 = r0 + 8;

    for (int l = 0; l < 7; l++) {
        const int K16 = (l == 0) ? 1 : 8;
        const int cur = l & 1;

        // weights for layer l ready
        cp_wait_all();
        __syncthreads();

        // kick off next layer's weights + bias into the other buffer;
        // the copy overlaps this layer's MMAs.
        if (l < 6) {
            const char* src = (const char*)(d_wpack + (size_t)(l + 1) * 32768);
            uint32_t dst = sb + ((l + 1) & 1) * SM_WBUF;
            for (int i = tid; i < 2048; i += 256)
                cp_async16(dst + 16 * i, src + 16 * (size_t)i);
            if (tid < 32)
                cp_async16(sb + SM_BIAS + ((l + 1) & 1) * 512 + 16 * tid,
                           (const char*)p.B[l + 1] + 16 * tid);
            cp_commit();
        }

        float acc[16][4];
#pragma unroll
        for (int j = 0; j < 16; j++)
#pragma unroll
            for (int q = 0; q < 4; q++) acc[j][q] = 0.0f;

        const uint4* wf = wbuf[cur];
#pragma unroll 1
        for (int ks = 0; ks < K16; ks++) {
#pragma unroll
            for (int jp = 0; jp < 8; jp++) {
                uint4 w = wf[(ks * 8 + jp) * 32 + lane];
                mma_fp16(acc[2 * jp],     af[ks], w.x, w.y);
                mma_fp16(acc[2 * jp + 1], af[ks], w.z, w.w);
            }
        }

        const float* bs = bias[cur];
        if (l < 6) {
            // bias + relu, repack D -> next-layer A fragments (lane-local)
#pragma unroll
            for (int j = 0; j < 16; j++) {
                float b0 = bs[8 * j + 2 * tc];
                float b1 = bs[8 * j + 2 * tc + 1];
                acc[j][0] = fmaxf(acc[j][0] + b0, 0.0f);
                acc[j][1] = fmaxf(acc[j][1] + b1, 0.0f);
                acc[j][2] = fmaxf(acc[j][2] + b0, 0.0f);
                acc[j][3] = fmaxf(acc[j][3] + b1, 0.0f);
            }
#pragma unroll
            for (int t = 0; t < 8; t++) {
                af[t][0] = cvt_f16x2(acc[2 * t][0],     acc[2 * t][1]);
                af[t][1] = cvt_f16x2(acc[2 * t][2],     acc[2 * t][3]);
                af[t][2] = cvt_f16x2(acc[2 * t + 1][0], acc[2 * t + 1][1]);
                af[t][3] = cvt_f16x2(acc[2 * t + 1][2], acc[2 * t + 1][3]);
            }
        } else {
            float* o0 = out + (size_t)r0 * 128;
            float* o1 = out + (size_t)r1 * 128;
#pragma unroll
            for (int j = 0; j < 16; j++) {
                const int col = 8 * j + 2 * tc;
                float b0 = bs[col], b1 = bs[col + 1];
                float2 v0 = make_float2(acc[j][0] + b0, acc[j][1] + b1);
                float2 v1 = make_float2(acc[j][2] + b0, acc[j][3] + b1);
                *(float2*)(o0 + col) = v0;
                *(float2*)(o1 + col) = v1;
            }
        }
    }
}

// ---------------- launch ----------------
extern "C" void kernel_launch(void* const* d_in, const int* in_sizes, int n_in,
                              void* d_out, int out_size) {
    const float* x    = (const float*)d_in[0];
    const float* g0   = (const float*)d_in[1];
    const float* g1   = (const float*)d_in[2];
    const float* g2   = (const float*)d_in[3];
    const float* g3   = (const float*)d_in[4];
    const float* coef = (const float*)d_in[5];

    MLPW p;
    for (int j = 0; j < 7; j++) {
        p.W[j] = (const float*)d_in[6 + 2 * j];
        p.B[j] = (const float*)d_in[7 + 2 * j];
    }
    float* out = (float*)d_out;

    cudaFuncSetAttribute(mlp_mma, cudaFuncAttributeMaxDynamicSharedMemorySize, SM_DYN);

    void* ptr;
    cudaGetSymbolAddress(&ptr, d_g0t);   float4* g0t = (float4*)ptr;
    cudaGetSymbolAddress(&ptr, d_g1t);   float4* g1t = (float4*)ptr;
    cudaGetSymbolAddress(&ptr, d_g2t);   float4* g2t = (float4*)ptr;
    cudaGetSymbolAddress(&ptr, d_g3t);   float4* g3t = (float4*)ptr;
    cudaGetSymbolAddress(&ptr, d_coeft); float4* ct  = (float4*)ptr;

    transpose_cl<<<(32 * 32 * 32 + 255) / 256, 256>>>(g0, g0t, 32 * 32 * 32);
    transpose_cl<<<(64 * 64 * 64 + 255) / 256, 256>>>(g1, g1t, 64 * 64 * 64);
    transpose_cl<<<(128 * 128 * 128 + 255) / 256, 256>>>(g2, g2t, 128 * 128 * 128);
    transpose_cl<<<(256 * 256 * 256 + 255) / 256, 256>>>(g3, g3t, 256 * 256 * 256);
    transpose_cl<<<(64 * 64 * 64 + 255) / 256, 256>>>(coef, ct, 64 * 64 * 64);

    pack_weights<<<(7 * 8 * 16 * 32 + 255) / 256, 256>>>(p);

    mlp_mma<<<N_PTS / 128, 256, SM_DYN>>>(p, x, out);
}